// round 6
// baseline (speedup 1.0000x reference)
#include <cuda_runtime.h>
#include <cstdint>

// ---------------- problem constants ----------------
#define HW   196
#define BB   8
#define SEQ  32
#define DD   768
#define DH   192
#define HALF 96                  // DH/2
#define NSEQ (BB*HW)             // 1568
#define MTOT (NSEQ*SEQ)          // 50176

// ---------------- scratch (__device__ globals) ------------------------------
__device__ float g_xd [MTOT*DH];
__device__ float g_q  [MTOT*DH];
__device__ float g_k  [MTOT*DH];
__device__ float g_v  [MTOT*DH];
__device__ float g_ret[MTOT*DH];

// xPos tables: [t (0..31)][p (0..95)]
__device__ float g_cos_u[SEQ*HALF];
__device__ float g_sin_u[SEQ*HALF];
__device__ float g_cos_d[SEQ*HALF];
__device__ float g_sin_d[SEQ*HALF];

// row m of the logical xr[(b*hw), s, D] maps to this row of x[(hw), b*s, D]
__device__ __forceinline__ int x_row_of(int m) {
    int q  = m >> 5;
    int t  = m & 31;
    int bi = q / HW;
    int hi = q - bi * HW;
    return hi * (BB * SEQ) + bi * SEQ + t;
}

// ---------------- packed f32x2 helpers (sm_100-family PTX) ------------------
__device__ __forceinline__ uint64_t pack_dup(float x) {
    uint64_t r;
    asm("mov.b64 %0, {%1, %1};" : "=l"(r) : "f"(x));
    return r;
}
__device__ __forceinline__ void fma2(uint64_t& d, uint64_t a, uint64_t b) {
    asm("fma.rn.f32x2 %0, %1, %2, %0;" : "+l"(d) : "l"(a), "l"(b));
}
__device__ __forceinline__ float2 unpack2(uint64_t v) {
    float2 f;
    asm("mov.b64 {%0, %1}, %2;" : "=f"(f.x), "=f"(f.y) : "l"(v));
    return f;
}

// ---------------- xPos table precompute (fp64) ------------------------------
__global__ void k_tables() {
    int i = blockIdx.x * blockDim.x + threadIdx.x;
    if (i >= SEQ * HALF) return;
    int t = i / HALF, p = i % HALF;
    double base = (2.0 * p + 0.4 * (double)DH) / (1.4 * (double)DH);
    double sc_u = pow(base, (double)t / 512.0);
    double sc_d = 1.0 / sc_u;
    double invf = pow(10000.0, -(double)p / (double)HALF);
    double ang  = (double)t * invf;
    double s = sin(ang), c = cos(ang);
    g_cos_u[i] = (float)(c * sc_u);
    g_sin_u[i] = (float)(s * sc_u);
    g_cos_d[i] = (float)(c * sc_d);
    g_sin_d[i] = (float)(s * sc_d);
}

// ---------------- tiled SGEMM with packed f32x2 FMAs ------------------------
// BM=128, BK=16, microtile 8x8 (acc packed as 8x4 f32x2), double-buffered smem.
// MODE 0: A gathered from x, +bias           -> C
// MODE 1: xPos upscale epilogue              -> C
// MODE 2: xPos downscale epilogue            -> C
// MODE 3: plain                              -> C
// MODE 4: +bias +x residual (gathered), gathered store -> C
template <int MODE, int BN>
__global__ void __launch_bounds__((BN/8)*16) k_gemm(
    const float* __restrict__ A, const float* __restrict__ B,
    const float* __restrict__ bias, const float* __restrict__ xres,
    float* __restrict__ C, int K, int N)
{
    constexpr int BM = 128, BK = 16;
    constexpr int THREADS  = (BN / 8) * 16;
    constexpr int AMP      = 132;
    constexpr int A_F4_PER = (BM * BK / 4) / THREADS;   // 4 (BN=64) or 2 (BN=128)
    constexpr int B_F4_PER = (BK * BN / 4) / THREADS;   // 2

    __shared__ __align__(16) float As[2][BK][AMP];
    __shared__ __align__(16) float Bs[2][BK][BN];

    const int tid = threadIdx.x;
    const int txx = tid % (BN / 8);
    const int tyy = tid / (BN / 8);
    const int bm  = blockIdx.y * BM;
    const int bn  = blockIdx.x * BN;

    int aRow[A_F4_PER], aKq[A_F4_PER];
    const float* aPtr[A_F4_PER];
#pragma unroll
    for (int i = 0; i < A_F4_PER; i++) {
        int f4 = tid + i * THREADS;
        aRow[i] = f4 >> 2;
        aKq[i]  = f4 & 3;
        int gm  = bm + aRow[i];
        int gr  = (MODE == 0) ? x_row_of(gm) : gm;
        aPtr[i] = A + (size_t)gr * K + aKq[i] * 4;
    }
    int bRow[B_F4_PER], bCol[B_F4_PER];
#pragma unroll
    for (int i = 0; i < B_F4_PER; i++) {
        int f4 = tid + i * THREADS;
        bRow[i] = f4 / (BN / 4);
        bCol[i] = (f4 % (BN / 4)) * 4;
    }

    // packed accumulators: acc2[r][cp] holds columns {2cp, 2cp+1} of row r
    uint64_t acc2[8][4];
#pragma unroll
    for (int r = 0; r < 8; r++)
#pragma unroll
        for (int cp = 0; cp < 4; cp++) acc2[r][cp] = 0ull;

    float4 aReg[A_F4_PER], bReg[B_F4_PER];

    auto loadG = [&](int k0) {
#pragma unroll
        for (int i = 0; i < A_F4_PER; i++)
            aReg[i] = *(const float4*)(aPtr[i] + k0);
#pragma unroll
        for (int i = 0; i < B_F4_PER; i++)
            bReg[i] = *(const float4*)(B + (size_t)(k0 + bRow[i]) * N + bn + bCol[i]);
    };
    auto storeS = [&](int buf) {
#pragma unroll
        for (int i = 0; i < A_F4_PER; i++) {
            As[buf][aKq[i] * 4 + 0][aRow[i]] = aReg[i].x;
            As[buf][aKq[i] * 4 + 1][aRow[i]] = aReg[i].y;
            As[buf][aKq[i] * 4 + 2][aRow[i]] = aReg[i].z;
            As[buf][aKq[i] * 4 + 3][aRow[i]] = aReg[i].w;
        }
#pragma unroll
        for (int i = 0; i < B_F4_PER; i++)
            *(float4*)&Bs[buf][bRow[i]][bCol[i]] = bReg[i];
    };
    auto compute = [&](int buf) {
#pragma unroll
        for (int kk = 0; kk < BK; kk++) {
            float a[8];
            *(float4*)&a[0] = *(const float4*)&As[buf][kk][tyy * 8];
            *(float4*)&a[4] = *(const float4*)&As[buf][kk][tyy * 8 + 4];
            uint64_t b2[4];
            const uint64_t* bp = (const uint64_t*)&Bs[buf][kk][txx * 8];
            b2[0] = bp[0]; b2[1] = bp[1]; b2[2] = bp[2]; b2[3] = bp[3];
            uint64_t a2[8];
#pragma unroll
            for (int r = 0; r < 8; r++) a2[r] = pack_dup(a[r]);
#pragma unroll
            for (int r = 0; r < 8; r++)
#pragma unroll
                for (int cp = 0; cp < 4; cp++)
                    fma2(acc2[r][cp], a2[r], b2[cp]);
        }
    };

    loadG(0);
    storeS(0);
    __syncthreads();
    int cur = 0;
    for (int k0 = BK; k0 < K; k0 += BK) {
        loadG(k0);
        compute(cur);
        storeS(cur ^ 1);
        __syncthreads();
        cur ^= 1;
    }
    compute(cur);

    // unpack to plain fp32 accumulator tile
    float acc[8][8];
#pragma unroll
    for (int r = 0; r < 8; r++)
#pragma unroll
        for (int cp = 0; cp < 4; cp++) {
            float2 t = unpack2(acc2[r][cp]);
            acc[r][2 * cp]     = t.x;
            acc[r][2 * cp + 1] = t.y;
        }

    const int m0 = bm + tyy * 8;
    const int n0 = bn + txx * 8;

    if (MODE == 0) {
        float bv[8];
        *(float4*)&bv[0] = *(const float4*)(bias + n0);
        *(float4*)&bv[4] = *(const float4*)(bias + n0 + 4);
#pragma unroll
        for (int r = 0; r < 8; r++) {
            float o[8];
#pragma unroll
            for (int c = 0; c < 8; c++) o[c] = acc[r][c] + bv[c];
            *(float4*)(C + (size_t)(m0 + r) * N + n0)     = *(float4*)&o[0];
            *(float4*)(C + (size_t)(m0 + r) * N + n0 + 4) = *(float4*)&o[4];
        }
    } else if (MODE == 1 || MODE == 2) {
        const float* ct = (MODE == 1) ? g_cos_u : g_cos_d;
        const float* st = (MODE == 1) ? g_sin_u : g_sin_d;
        const int p0 = n0 >> 1;
#pragma unroll
        for (int r = 0; r < 8; r++) {
            int m = m0 + r;
            int t = m & 31;
            float o[8];
#pragma unroll
            for (int pp = 0; pp < 4; pp++) {
                float cc = ct[t * HALF + p0 + pp];
                float ss = st[t * HALF + p0 + pp];
                float e = acc[r][pp * 2], od = acc[r][pp * 2 + 1];
                o[pp * 2]     = e * cc - od * ss;
                o[pp * 2 + 1] = od * cc + e * ss;
            }
            *(float4*)(C + (size_t)m * N + n0)     = *(float4*)&o[0];
            *(float4*)(C + (size_t)m * N + n0 + 4) = *(float4*)&o[4];
        }
    } else if (MODE == 3) {
#pragma unroll
        for (int r = 0; r < 8; r++) {
            *(float4*)(C + (size_t)(m0 + r) * N + n0)     = *(float4*)&acc[r][0];
            *(float4*)(C + (size_t)(m0 + r) * N + n0 + 4) = *(float4*)&acc[r][4];
        }
    } else { // MODE 4
        float bv[8];
        *(float4*)&bv[0] = *(const float4*)(bias + n0);
        *(float4*)&bv[4] = *(const float4*)(bias + n0 + 4);
#pragma unroll
        for (int r = 0; r < 8; r++) {
            int gr = x_row_of(m0 + r);
            size_t base = (size_t)gr * N + n0;
            float4 x0 = *(const float4*)(xres + base);
            float4 x1 = *(const float4*)(xres + base + 4);
            float o[8];
            o[0] = acc[r][0] + bv[0] + x0.x; o[1] = acc[r][1] + bv[1] + x0.y;
            o[2] = acc[r][2] + bv[2] + x0.z; o[3] = acc[r][3] + bv[3] + x0.w;
            o[4] = acc[r][4] + bv[4] + x1.x; o[5] = acc[r][5] + bv[5] + x1.y;
            o[6] = acc[r][6] + bv[6] + x1.z; o[7] = acc[r][7] + bv[7] + x1.w;
            *(float4*)(C + base)     = *(float4*)&o[0];
            *(float4*)(C + base + 4) = *(float4*)&o[4];
        }
    }
}

// ---------------- LayerNorm over d=192 (one warp per row, in place) --------
__global__ void k_ln(float* __restrict__ xd,
                     const float* __restrict__ g, const float* __restrict__ b)
{
    int gwarp = (blockIdx.x * blockDim.x + threadIdx.x) >> 5;
    int lane  = threadIdx.x & 31;
    if (gwarp >= MTOT) return;
    float* row = xd + (size_t)gwarp * DH;
    float v[6];
    float s = 0.0f;
#pragma unroll
    for (int i = 0; i < 6; i++) { v[i] = row[lane + 32 * i]; s += v[i]; }
#pragma unroll
    for (int o = 16; o; o >>= 1) s += __shfl_xor_sync(0xffffffffu, s, o);
    float mu = s * (1.0f / DH);
    float vs = 0.0f;
#pragma unroll
    for (int i = 0; i < 6; i++) { float d = v[i] - mu; vs += d * d; }
#pragma unroll
    for (int o = 16; o; o >>= 1) vs += __shfl_xor_sync(0xffffffffu, vs, o);
    float inv = rsqrtf(vs * (1.0f / DH) + 1e-5f);
#pragma unroll
    for (int i = 0; i < 6; i++) {
        int c = lane + 32 * i;
        row[c] = (v[i] - mu) * inv * g[c] + b[c];
    }
}

// ---------------- per-sequence retention attention -------------------------
__global__ void __launch_bounds__(256) k_attn(
    const float* __restrict__ Q, const float* __restrict__ Kmat,
    const float* __restrict__ V, float* __restrict__ R)
{
    __shared__ __align__(16) float sKV[SEQ][DH];
    const int q   = blockIdx.x;
    const int tid = threadIdx.x;
    const int n   = tid >> 3;
    const int j   = tid & 7;
    const size_t base = (size_t)q * SEQ * DH;

    for (int i = tid; i < SEQ * DH / 4; i += 256)
        ((float4*)&sKV[0][0])[i] = ((const float4*)(Kmat + base))[i];

    float qr[24];
    const float* qp = Q + base + (size_t)n * DH + j * 24;
#pragma unroll
    for (int dd = 0; dd < 6; dd++)
        *(float4*)&qr[dd * 4] = *(const float4*)(qp + dd * 4);
    __syncthreads();

    float att[SEQ];
#pragma unroll
    for (int m = 0; m < SEQ; m++) {
        float s = 0.0f;
#pragma unroll
        for (int dd = 0; dd < 6; dd++) {
            float4 kv = *(const float4*)&sKV[m][j * 24 + dd * 4];
            s += qr[dd*4+0]*kv.x + qr[dd*4+1]*kv.y + qr[dd*4+2]*kv.z + qr[dd*4+3]*kv.w;
        }
        att[m] = s;
    }
#pragma unroll
    for (int m = 0; m < SEQ; m++) {
#pragma unroll
        for (int o = 1; o < 8; o <<= 1)
            att[m] += __shfl_xor_sync(0xffffffffu, att[m], o);
        att[m] = (n >= m) ? ldexpf(att[m], m - n) : 0.0f;
    }

    __syncthreads();
    for (int i = tid; i < SEQ * DH / 4; i += 256)
        ((float4*)&sKV[0][0])[i] = ((const float4*)(V + base))[i];
    __syncthreads();

    float acc[24];
#pragma unroll
    for (int dd = 0; dd < 24; dd++) acc[dd] = 0.0f;
#pragma unroll
    for (int m = 0; m < SEQ; m++) {
        float a = att[m];
#pragma unroll
        for (int dd = 0; dd < 6; dd++) {
            float4 vv = *(const float4*)&sKV[m][j * 24 + dd * 4];
            acc[dd*4+0] += a * vv.x; acc[dd*4+1] += a * vv.y;
            acc[dd*4+2] += a * vv.z; acc[dd*4+3] += a * vv.w;
        }
    }
    float* rp = R + base + (size_t)n * DH + j * 24;
#pragma unroll
    for (int dd = 0; dd < 6; dd++)
        *(float4*)(rp + dd * 4) = *(const float4*)&acc[dd * 4];
}

// ---------------- launch --------------------------------------------------
extern "C" void kernel_launch(void* const* d_in, const int* in_sizes, int n_in,
                              void* d_out, int out_size)
{
    const float* x    = (const float*)d_in[0];
    const float* W1   = (const float*)d_in[1];
    const float* b1   = (const float*)d_in[2];
    const float* W2   = (const float*)d_in[3];
    const float* b2   = (const float*)d_in[4];
    const float* ln_g = (const float*)d_in[5];
    const float* ln_b = (const float*)d_in[6];
    const float* WQ   = (const float*)d_in[7];
    const float* WK   = (const float*)d_in[8];
    const float* WV   = (const float*)d_in[9];
    float* out = (float*)d_out;

    float* xd = nullptr; cudaGetSymbolAddress((void**)&xd, g_xd);
    float* qb = nullptr; cudaGetSymbolAddress((void**)&qb, g_q);
    float* kb = nullptr; cudaGetSymbolAddress((void**)&kb, g_k);
    float* vb = nullptr; cudaGetSymbolAddress((void**)&vb, g_v);
    float* rb = nullptr; cudaGetSymbolAddress((void**)&rb, g_ret);

    k_tables<<<12, 256>>>();

    // GEMM1: x(gathered) @ W1 + b1 -> g_xd   [M=50176, K=768, N=192]
    k_gemm<0, 64><<<dim3(DH / 64, MTOT / 128), 128>>>(x, W1, b1, nullptr, xd, DD, DH);
    k_ln<<<MTOT / 8, 256>>>(xd, ln_g, ln_b);
    // QKV: h @ W{Q,K,V}  [M=50176, K=192, N=192]
    k_gemm<1, 64><<<dim3(DH / 64, MTOT / 128), 128>>>(xd, WQ, nullptr, nullptr, qb, DH, DH);
    k_gemm<2, 64><<<dim3(DH / 64, MTOT / 128), 128>>>(xd, WK, nullptr, nullptr, kb, DH, DH);
    k_gemm<3, 64><<<dim3(DH / 64, MTOT / 128), 128>>>(xd, WV, nullptr, nullptr, vb, DH, DH);
    k_attn<<<NSEQ, 256>>>(qb, kb, vb, rb);
    // GEMM2: ret @ W2 + b2 + x (residual) -> d_out  [M=50176, K=192, N=768]
    k_gemm<4, 128><<<dim3(DD / 128, MTOT / 128), 256>>>(rb, W2, b2, x, out, DH, DD);
}

// round 7
// speedup vs baseline: 1.0011x; 1.0011x over previous
#include <cuda_runtime.h>
#include <cstdint>

// ---------------- problem constants ----------------
#define HW   196
#define BB   8
#define SEQ  32
#define DD   768
#define DH   192
#define HALF 96                  // DH/2
#define NSEQ (BB*HW)             // 1568
#define MTOT (NSEQ*SEQ)          // 50176

// ---------------- scratch (__device__ globals) ------------------------------
__device__ float g_xd [MTOT*DH];
__device__ float g_q  [MTOT*DH];
__device__ float g_k  [MTOT*DH];
__device__ float g_v  [MTOT*DH];
__device__ float g_ret[MTOT*DH];

// xPos tables: [t (0..31)][p (0..95)]
__device__ float g_cos_u[SEQ*HALF];
__device__ float g_sin_u[SEQ*HALF];
__device__ float g_cos_d[SEQ*HALF];
__device__ float g_sin_d[SEQ*HALF];

// row m of the logical xr[(b*hw), s, D] maps to this row of x[(hw), b*s, D]
__device__ __forceinline__ int x_row_of(int m) {
    int q  = m >> 5;
    int t  = m & 31;
    int bi = q / HW;
    int hi = q - bi * HW;
    return hi * (BB * SEQ) + bi * SEQ + t;
}

// ---------------- packed f32x2 helpers (sm_100-family PTX) ------------------
__device__ __forceinline__ uint64_t pack_dup(float x) {
    uint64_t r;
    asm("mov.b64 %0, {%1, %1};" : "=l"(r) : "f"(x));
    return r;
}
__device__ __forceinline__ void fma2(uint64_t& d, uint64_t a, uint64_t b) {
    asm("fma.rn.f32x2 %0, %1, %2, %0;" : "+l"(d) : "l"(a), "l"(b));
}
__device__ __forceinline__ float2 unpack2(uint64_t v) {
    float2 f;
    asm("mov.b64 {%0, %1}, %2;" : "=f"(f.x), "=f"(f.y) : "l"(v));
    return f;
}

// ---------------- xPos table precompute (fp64) ------------------------------
__global__ void k_tables() {
    int i = blockIdx.x * blockDim.x + threadIdx.x;
    if (i >= SEQ * HALF) return;
    int t = i / HALF, p = i % HALF;
    double base = (2.0 * p + 0.4 * (double)DH) / (1.4 * (double)DH);
    double sc_u = pow(base, (double)t / 512.0);
    double sc_d = 1.0 / sc_u;
    double invf = pow(10000.0, -(double)p / (double)HALF);
    double ang  = (double)t * invf;
    double s = sin(ang), c = cos(ang);
    g_cos_u[i] = (float)(c * sc_u);
    g_sin_u[i] = (float)(s * sc_u);
    g_cos_d[i] = (float)(c * sc_d);
    g_sin_d[i] = (float)(s * sc_d);
}

// ---------------- tiled SGEMM with packed f32x2 FMAs ------------------------
// BM=128, BK=16, microtile 8x8 (acc packed as 8x4 f32x2), double-buffered smem.
// MODE 0: A gathered from x, +bias           -> C
// MODE 1: xPos upscale epilogue              -> C
// MODE 2: xPos downscale epilogue            -> C
// MODE 3: plain                              -> C
// MODE 4: +bias +x residual (gathered), gathered store -> C
template <int MODE, int BN>
__global__ void __launch_bounds__((BN/8)*16) k_gemm(
    const float* __restrict__ A, const float* __restrict__ B,
    const float* __restrict__ bias, const float* __restrict__ xres,
    float* __restrict__ C, int K, int N)
{
    constexpr int BM = 128, BK = 16;
    constexpr int THREADS  = (BN / 8) * 16;
    constexpr int AMP      = 132;
    constexpr int A_F4_PER = (BM * BK / 4) / THREADS;   // 4 (BN=64) or 2 (BN=128)
    constexpr int B_F4_PER = (BK * BN / 4) / THREADS;   // 2

    __shared__ __align__(16) float As[2][BK][AMP];
    __shared__ __align__(16) float Bs[2][BK][BN];

    const int tid = threadIdx.x;
    const int txx = tid % (BN / 8);
    const int tyy = tid / (BN / 8);
    const int bm  = blockIdx.y * BM;
    const int bn  = blockIdx.x * BN;

    int aRow[A_F4_PER], aKq[A_F4_PER];
    const float* aPtr[A_F4_PER];
#pragma unroll
    for (int i = 0; i < A_F4_PER; i++) {
        int f4 = tid + i * THREADS;
        aRow[i] = f4 >> 2;
        aKq[i]  = f4 & 3;
        int gm  = bm + aRow[i];
        int gr  = (MODE == 0) ? x_row_of(gm) : gm;
        aPtr[i] = A + (size_t)gr * K + aKq[i] * 4;
    }
    int bRow[B_F4_PER], bCol[B_F4_PER];
#pragma unroll
    for (int i = 0; i < B_F4_PER; i++) {
        int f4 = tid + i * THREADS;
        bRow[i] = f4 / (BN / 4);
        bCol[i] = (f4 % (BN / 4)) * 4;
    }

    // packed accumulators: acc2[r][cp] holds columns {2cp, 2cp+1} of row r
    uint64_t acc2[8][4];
#pragma unroll
    for (int r = 0; r < 8; r++)
#pragma unroll
        for (int cp = 0; cp < 4; cp++) acc2[r][cp] = 0ull;

    float4 aReg[A_F4_PER], bReg[B_F4_PER];

    auto loadG = [&](int k0) {
#pragma unroll
        for (int i = 0; i < A_F4_PER; i++)
            aReg[i] = *(const float4*)(aPtr[i] + k0);
#pragma unroll
        for (int i = 0; i < B_F4_PER; i++)
            bReg[i] = *(const float4*)(B + (size_t)(k0 + bRow[i]) * N + bn + bCol[i]);
    };
    auto storeS = [&](int buf) {
#pragma unroll
        for (int i = 0; i < A_F4_PER; i++) {
            As[buf][aKq[i] * 4 + 0][aRow[i]] = aReg[i].x;
            As[buf][aKq[i] * 4 + 1][aRow[i]] = aReg[i].y;
            As[buf][aKq[i] * 4 + 2][aRow[i]] = aReg[i].z;
            As[buf][aKq[i] * 4 + 3][aRow[i]] = aReg[i].w;
        }
#pragma unroll
        for (int i = 0; i < B_F4_PER; i++)
            *(float4*)&Bs[buf][bRow[i]][bCol[i]] = bReg[i];
    };
    auto compute = [&](int buf) {
#pragma unroll
        for (int kk = 0; kk < BK; kk++) {
            float a[8];
            *(float4*)&a[0] = *(const float4*)&As[buf][kk][tyy * 8];
            *(float4*)&a[4] = *(const float4*)&As[buf][kk][tyy * 8 + 4];
            uint64_t b2[4];
            const uint64_t* bp = (const uint64_t*)&Bs[buf][kk][txx * 8];
            b2[0] = bp[0]; b2[1] = bp[1]; b2[2] = bp[2]; b2[3] = bp[3];
            uint64_t a2[8];
#pragma unroll
            for (int r = 0; r < 8; r++) a2[r] = pack_dup(a[r]);
#pragma unroll
            for (int r = 0; r < 8; r++)
#pragma unroll
                for (int cp = 0; cp < 4; cp++)
                    fma2(acc2[r][cp], a2[r], b2[cp]);
        }
    };

    loadG(0);
    storeS(0);
    __syncthreads();
    int cur = 0;
    for (int k0 = BK; k0 < K; k0 += BK) {
        loadG(k0);
        compute(cur);
        storeS(cur ^ 1);
        __syncthreads();
        cur ^= 1;
    }
    compute(cur);

    // unpack to plain fp32 accumulator tile
    float acc[8][8];
#pragma unroll
    for (int r = 0; r < 8; r++)
#pragma unroll
        for (int cp = 0; cp < 4; cp++) {
            float2 t = unpack2(acc2[r][cp]);
            acc[r][2 * cp]     = t.x;
            acc[r][2 * cp + 1] = t.y;
        }

    const int m0 = bm + tyy * 8;
    const int n0 = bn + txx * 8;

    if (MODE == 0) {
        float bv[8];
        *(float4*)&bv[0] = *(const float4*)(bias + n0);
        *(float4*)&bv[4] = *(const float4*)(bias + n0 + 4);
#pragma unroll
        for (int r = 0; r < 8; r++) {
            float o[8];
#pragma unroll
            for (int c = 0; c < 8; c++) o[c] = acc[r][c] + bv[c];
            *(float4*)(C + (size_t)(m0 + r) * N + n0)     = *(float4*)&o[0];
            *(float4*)(C + (size_t)(m0 + r) * N + n0 + 4) = *(float4*)&o[4];
        }
    } else if (MODE == 1 || MODE == 2) {
        const float* ct = (MODE == 1) ? g_cos_u : g_cos_d;
        const float* st = (MODE == 1) ? g_sin_u : g_sin_d;
        const int p0 = n0 >> 1;
#pragma unroll
        for (int r = 0; r < 8; r++) {
            int m = m0 + r;
            int t = m & 31;
            float o[8];
#pragma unroll
            for (int pp = 0; pp < 4; pp++) {
                float cc = ct[t * HALF + p0 + pp];
                float ss = st[t * HALF + p0 + pp];
                float e = acc[r][pp * 2], od = acc[r][pp * 2 + 1];
                o[pp * 2]     = e * cc - od * ss;
                o[pp * 2 + 1] = od * cc + e * ss;
            }
            *(float4*)(C + (size_t)m * N + n0)     = *(float4*)&o[0];
            *(float4*)(C + (size_t)m * N + n0 + 4) = *(float4*)&o[4];
        }
    } else if (MODE == 3) {
#pragma unroll
        for (int r = 0; r < 8; r++) {
            *(float4*)(C + (size_t)(m0 + r) * N + n0)     = *(float4*)&acc[r][0];
            *(float4*)(C + (size_t)(m0 + r) * N + n0 + 4) = *(float4*)&acc[r][4];
        }
    } else { // MODE 4
        float bv[8];
        *(float4*)&bv[0] = *(const float4*)(bias + n0);
        *(float4*)&bv[4] = *(const float4*)(bias + n0 + 4);
#pragma unroll
        for (int r = 0; r < 8; r++) {
            int gr = x_row_of(m0 + r);
            size_t base = (size_t)gr * N + n0;
            float4 x0 = *(const float4*)(xres + base);
            float4 x1 = *(const float4*)(xres + base + 4);
            float o[8];
            o[0] = acc[r][0] + bv[0] + x0.x; o[1] = acc[r][1] + bv[1] + x0.y;
            o[2] = acc[r][2] + bv[2] + x0.z; o[3] = acc[r][3] + bv[3] + x0.w;
            o[4] = acc[r][4] + bv[4] + x1.x; o[5] = acc[r][5] + bv[5] + x1.y;
            o[6] = acc[r][6] + bv[6] + x1.z; o[7] = acc[r][7] + bv[7] + x1.w;
            *(float4*)(C + base)     = *(float4*)&o[0];
            *(float4*)(C + base + 4) = *(float4*)&o[4];
        }
    }
}

// ---------------- LayerNorm over d=192 (one warp per row, in place) --------
__global__ void k_ln(float* __restrict__ xd,
                     const float* __restrict__ g, const float* __restrict__ b)
{
    int gwarp = (blockIdx.x * blockDim.x + threadIdx.x) >> 5;
    int lane  = threadIdx.x & 31;
    if (gwarp >= MTOT) return;
    float* row = xd + (size_t)gwarp * DH;
    float v[6];
    float s = 0.0f;
#pragma unroll
    for (int i = 0; i < 6; i++) { v[i] = row[lane + 32 * i]; s += v[i]; }
#pragma unroll
    for (int o = 16; o; o >>= 1) s += __shfl_xor_sync(0xffffffffu, s, o);
    float mu = s * (1.0f / DH);
    float vs = 0.0f;
#pragma unroll
    for (int i = 0; i < 6; i++) { float d = v[i] - mu; vs += d * d; }
#pragma unroll
    for (int o = 16; o; o >>= 1) vs += __shfl_xor_sync(0xffffffffu, vs, o);
    float inv = rsqrtf(vs * (1.0f / DH) + 1e-5f);
#pragma unroll
    for (int i = 0; i < 6; i++) {
        int c = lane + 32 * i;
        row[c] = (v[i] - mu) * inv * g[c] + b[c];
    }
}

// ---------------- per-sequence retention attention -------------------------
__global__ void __launch_bounds__(256) k_attn(
    const float* __restrict__ Q, const float* __restrict__ Kmat,
    const float* __restrict__ V, float* __restrict__ R)
{
    __shared__ __align__(16) float sKV[SEQ][DH];
    const int q   = blockIdx.x;
    const int tid = threadIdx.x;
    const int n   = tid >> 3;
    const int j   = tid & 7;
    const size_t base = (size_t)q * SEQ * DH;

    for (int i = tid; i < SEQ * DH / 4; i += 256)
        ((float4*)&sKV[0][0])[i] = ((const float4*)(Kmat + base))[i];

    float qr[24];
    const float* qp = Q + base + (size_t)n * DH + j * 24;
#pragma unroll
    for (int dd = 0; dd < 6; dd++)
        *(float4*)&qr[dd * 4] = *(const float4*)(qp + dd * 4);
    __syncthreads();

    float att[SEQ];
#pragma unroll
    for (int m = 0; m < SEQ; m++) {
        float s = 0.0f;
#pragma unroll
        for (int dd = 0; dd < 6; dd++) {
            float4 kv = *(const float4*)&sKV[m][j * 24 + dd * 4];
            s += qr[dd*4+0]*kv.x + qr[dd*4+1]*kv.y + qr[dd*4+2]*kv.z + qr[dd*4+3]*kv.w;
        }
        att[m] = s;
    }
#pragma unroll
    for (int m = 0; m < SEQ; m++) {
#pragma unroll
        for (int o = 1; o < 8; o <<= 1)
            att[m] += __shfl_xor_sync(0xffffffffu, att[m], o);
        att[m] = (n >= m) ? ldexpf(att[m], m - n) : 0.0f;
    }

    __syncthreads();
    for (int i = tid; i < SEQ * DH / 4; i += 256)
        ((float4*)&sKV[0][0])[i] = ((const float4*)(V + base))[i];
    __syncthreads();

    float acc[24];
#pragma unroll
    for (int dd = 0; dd < 24; dd++) acc[dd] = 0.0f;
#pragma unroll
    for (int m = 0; m < SEQ; m++) {
        float a = att[m];
#pragma unroll
        for (int dd = 0; dd < 6; dd++) {
            float4 vv = *(const float4*)&sKV[m][j * 24 + dd * 4];
            acc[dd*4+0] += a * vv.x; acc[dd*4+1] += a * vv.y;
            acc[dd*4+2] += a * vv.z; acc[dd*4+3] += a * vv.w;
        }
    }
    float* rp = R + base + (size_t)n * DH + j * 24;
#pragma unroll
    for (int dd = 0; dd < 6; dd++)
        *(float4*)(rp + dd * 4) = *(const float4*)&acc[dd * 4];
}

// ---------------- launch --------------------------------------------------
extern "C" void kernel_launch(void* const* d_in, const int* in_sizes, int n_in,
                              void* d_out, int out_size)
{
    const float* x    = (const float*)d_in[0];
    const float* W1   = (const float*)d_in[1];
    const float* b1   = (const float*)d_in[2];
    const float* W2   = (const float*)d_in[3];
    const float* b2   = (const float*)d_in[4];
    const float* ln_g = (const float*)d_in[5];
    const float* ln_b = (const float*)d_in[6];
    const float* WQ   = (const float*)d_in[7];
    const float* WK   = (const float*)d_in[8];
    const float* WV   = (const float*)d_in[9];
    float* out = (float*)d_out;

    float* xd = nullptr; cudaGetSymbolAddress((void**)&xd, g_xd);
    float* qb = nullptr; cudaGetSymbolAddress((void**)&qb, g_q);
    float* kb = nullptr; cudaGetSymbolAddress((void**)&kb, g_k);
    float* vb = nullptr; cudaGetSymbolAddress((void**)&vb, g_v);
    float* rb = nullptr; cudaGetSymbolAddress((void**)&rb, g_ret);

    k_tables<<<12, 256>>>();

    // GEMM1: x(gathered) @ W1 + b1 -> g_xd   [M=50176, K=768, N=192]
    k_gemm<0, 64><<<dim3(DH / 64, MTOT / 128), 128>>>(x, W1, b1, nullptr, xd, DD, DH);
    k_ln<<<MTOT / 8, 256>>>(xd, ln_g, ln_b);
    // QKV: h @ W{Q,K,V}  [M=50176, K=192, N=192]
    k_gemm<1, 64><<<dim3(DH / 64, MTOT / 128), 128>>>(xd, WQ, nullptr, nullptr, qb, DH, DH);
    k_gemm<2, 64><<<dim3(DH / 64, MTOT / 128), 128>>>(xd, WK, nullptr, nullptr, kb, DH, DH);
    k_gemm<3, 64><<<dim3(DH / 64, MTOT / 128), 128>>>(xd, WV, nullptr, nullptr, vb, DH, DH);
    k_attn<<<NSEQ, 256>>>(qb, kb, vb, rb);
    // GEMM2: ret @ W2 + b2 + x (residual) -> d_out  [M=50176, K=192, N=768]
    k_gemm<4, 128><<<dim3(DD / 128, MTOT / 128), 256>>>(rb, W2, b2, x, out, DH, DD);
}

// round 8
// speedup vs baseline: 1.0540x; 1.0528x over previous
#include <cuda_runtime.h>
#include <cstdint>

// ---------------- problem constants ----------------
#define HW   196
#define BB   8
#define SEQ  32
#define DD   768
#define DH   192
#define HALF 96                  // DH/2
#define NSEQ (BB*HW)             // 1568
#define MTOT (NSEQ*SEQ)          // 50176

// ---------------- scratch (__device__ globals) ------------------------------
__device__ float g_xd [MTOT*DH];
__device__ float g_q  [MTOT*DH];
__device__ float g_k  [MTOT*DH];
__device__ float g_v  [MTOT*DH];
__device__ float g_ret[MTOT*DH];

// xPos tables: [t (0..31)][p (0..95)]
__device__ float g_cos_u[SEQ*HALF];
__device__ float g_sin_u[SEQ*HALF];
__device__ float g_cos_d[SEQ*HALF];
__device__ float g_sin_d[SEQ*HALF];

// row m of the logical xr[(b*hw), s, D] maps to this row of x[(hw), b*s, D]
__device__ __forceinline__ int x_row_of(int m) {
    int q  = m >> 5;
    int t  = m & 31;
    int bi = q / HW;
    int hi = q - bi * HW;
    return hi * (BB * SEQ) + bi * SEQ + t;
}

// ---------------- packed f32x2 helpers (sm_100-family PTX) ------------------
__device__ __forceinline__ uint64_t pack_dup(float x) {
    uint64_t r;
    asm("mov.b64 %0, {%1, %1};" : "=l"(r) : "f"(x));
    return r;
}
__device__ __forceinline__ void fma2(uint64_t& d, uint64_t a, uint64_t b) {
    asm("fma.rn.f32x2 %0, %1, %2, %0;" : "+l"(d) : "l"(a), "l"(b));
}
__device__ __forceinline__ float2 unpack2(uint64_t v) {
    float2 f;
    asm("mov.b64 {%0, %1}, %2;" : "=f"(f.x), "=f"(f.y) : "l"(v));
    return f;
}

// ---------------- xPos table precompute (fp64) ------------------------------
__global__ void k_tables() {
    int i = blockIdx.x * blockDim.x + threadIdx.x;
    if (i >= SEQ * HALF) return;
    int t = i / HALF, p = i % HALF;
    double base = (2.0 * p + 0.4 * (double)DH) / (1.4 * (double)DH);
    double sc_u = pow(base, (double)t / 512.0);
    double sc_d = 1.0 / sc_u;
    double invf = pow(10000.0, -(double)p / (double)HALF);
    double ang  = (double)t * invf;
    double s = sin(ang), c = cos(ang);
    g_cos_u[i] = (float)(c * sc_u);
    g_sin_u[i] = (float)(s * sc_u);
    g_cos_d[i] = (float)(c * sc_d);
    g_sin_d[i] = (float)(s * sc_d);
}

// ---------------- tiled SGEMM, packed f32x2, BM=128 BN=192 BK=16 ------------
// 256 threads, microtile 8 rows x 12 cols (acc 8x6 f32x2). Double-buffered.
// MODE 0: A gathered from x; +bias then fused LayerNorm            -> C
// MODE 1: xPos upscale epilogue                                    -> C
// MODE 2: xPos downscale epilogue                                  -> C
// MODE 3: plain                                                    -> C
// MODE 4: +bias +x residual (gathered rows), gathered store        -> C
template <int MODE>
__global__ void __launch_bounds__(256) k_gemm(
    const float* __restrict__ A, const float* __restrict__ B,
    const float* __restrict__ bias,
    const float* __restrict__ lng, const float* __restrict__ lnb,
    const float* __restrict__ xres,
    float* __restrict__ C, int K, int N)
{
    constexpr int BM = 128, BN = 192, BK = 16;
    constexpr int THREADS = 256;
    constexpr int AMP = 132;

    __shared__ __align__(16) float As[2][BK][AMP];
    __shared__ __align__(16) float Bs[2][BK][BN];

    const int tid = threadIdx.x;
    const int txx = tid & 15;          // N dir: 16 * 12 = 192
    const int tyy = tid >> 4;          // M dir: 16 * 8  = 128
    const int bm  = blockIdx.y * BM;
    const int bn  = blockIdx.x * BN;

    // A: 2 float4 per thread
    int aRow[2], aKq[2];
    const float* aPtr[2];
#pragma unroll
    for (int i = 0; i < 2; i++) {
        int f4 = tid + i * THREADS;
        aRow[i] = f4 >> 2;
        aKq[i]  = f4 & 3;
        int gm  = bm + aRow[i];
        int gr  = (MODE == 0) ? x_row_of(gm) : gm;
        aPtr[i] = A + (size_t)gr * K + aKq[i] * 4;
    }
    // B: 3 float4 per thread (row of 48 float4s)
    int bRow[3], bCol[3];
#pragma unroll
    for (int i = 0; i < 3; i++) {
        int f4 = tid + i * THREADS;
        bRow[i] = f4 / 48;
        bCol[i] = (f4 % 48) * 4;
    }

    // acc2[r][cp] = packed cols {2cp, 2cp+1} of row r
    uint64_t acc2[8][6];
#pragma unroll
    for (int r = 0; r < 8; r++)
#pragma unroll
        for (int cp = 0; cp < 6; cp++) acc2[r][cp] = 0ull;

    float4 aReg[2], bReg[3];

    auto loadG = [&](int k0) {
#pragma unroll
        for (int i = 0; i < 2; i++)
            aReg[i] = *(const float4*)(aPtr[i] + k0);
#pragma unroll
        for (int i = 0; i < 3; i++)
            bReg[i] = *(const float4*)(B + (size_t)(k0 + bRow[i]) * N + bn + bCol[i]);
    };
    auto storeS = [&](int buf) {
#pragma unroll
        for (int i = 0; i < 2; i++) {
            As[buf][aKq[i] * 4 + 0][aRow[i]] = aReg[i].x;
            As[buf][aKq[i] * 4 + 1][aRow[i]] = aReg[i].y;
            As[buf][aKq[i] * 4 + 2][aRow[i]] = aReg[i].z;
            As[buf][aKq[i] * 4 + 3][aRow[i]] = aReg[i].w;
        }
#pragma unroll
        for (int i = 0; i < 3; i++)
            *(float4*)&Bs[buf][bRow[i]][bCol[i]] = bReg[i];
    };
    auto compute = [&](int buf) {
#pragma unroll
        for (int kk = 0; kk < BK; kk++) {
            float a[8];
            *(float4*)&a[0] = *(const float4*)&As[buf][kk][tyy * 8];
            *(float4*)&a[4] = *(const float4*)&As[buf][kk][tyy * 8 + 4];
            uint64_t b2[6];
            const uint64_t* bp = (const uint64_t*)&Bs[buf][kk][txx * 12];
#pragma unroll
            for (int i = 0; i < 6; i++) b2[i] = bp[i];
            uint64_t a2[8];
#pragma unroll
            for (int r = 0; r < 8; r++) a2[r] = pack_dup(a[r]);
#pragma unroll
            for (int r = 0; r < 8; r++)
#pragma unroll
                for (int cp = 0; cp < 6; cp++)
                    fma2(acc2[r][cp], a2[r], b2[cp]);
        }
    };

    loadG(0);
    storeS(0);
    __syncthreads();
    int cur = 0;
    for (int k0 = BK; k0 < K; k0 += BK) {
        loadG(k0);
        compute(cur);
        storeS(cur ^ 1);
        __syncthreads();
        cur ^= 1;
    }
    compute(cur);

    // unpack
    float acc[8][12];
#pragma unroll
    for (int r = 0; r < 8; r++)
#pragma unroll
        for (int cp = 0; cp < 6; cp++) {
            float2 t = unpack2(acc2[r][cp]);
            acc[r][2 * cp]     = t.x;
            acc[r][2 * cp + 1] = t.y;
        }

    const int m0 = bm + tyy * 8;
    const int n0 = bn + txx * 12;

    if (MODE == 0) {
        // +bias, then LayerNorm across the 16 txx lanes (full 192-col row)
        float bv[12];
#pragma unroll
        for (int c = 0; c < 12; c++) bv[c] = __ldg(&bias[n0 + c]);
        float gv[12], be[12];
#pragma unroll
        for (int c = 0; c < 12; c++) { gv[c] = __ldg(&lng[n0 + c]); be[c] = __ldg(&lnb[n0 + c]); }
#pragma unroll
        for (int r = 0; r < 8; r++) {
            float s1 = 0.f, s2 = 0.f;
#pragma unroll
            for (int c = 0; c < 12; c++) {
                float v = acc[r][c] + bv[c];
                acc[r][c] = v;
                s1 += v; s2 += v * v;
            }
#pragma unroll
            for (int o = 1; o < 16; o <<= 1) {
                s1 += __shfl_xor_sync(0xffffffffu, s1, o);
                s2 += __shfl_xor_sync(0xffffffffu, s2, o);
            }
            float mu  = s1 * (1.0f / 192.0f);
            float inv = rsqrtf(s2 * (1.0f / 192.0f) - mu * mu + 1e-5f);
            float o12[12];
#pragma unroll
            for (int c = 0; c < 12; c++)
                o12[c] = (acc[r][c] - mu) * inv * gv[c] + be[c];
            float* cp = C + (size_t)(m0 + r) * N + n0;
            *(float4*)(cp + 0) = *(float4*)&o12[0];
            *(float4*)(cp + 4) = *(float4*)&o12[4];
            *(float4*)(cp + 8) = *(float4*)&o12[8];
        }
    } else if (MODE == 1 || MODE == 2) {
        const float* ct = (MODE == 1) ? g_cos_u : g_cos_d;
        const float* st = (MODE == 1) ? g_sin_u : g_sin_d;
        const int p0 = n0 >> 1;
#pragma unroll
        for (int r = 0; r < 8; r++) {
            int m = m0 + r;
            int t = m & 31;
            float o12[12];
#pragma unroll
            for (int pp = 0; pp < 6; pp++) {
                float cc = ct[t * HALF + p0 + pp];
                float ss = st[t * HALF + p0 + pp];
                float e = acc[r][pp * 2], od = acc[r][pp * 2 + 1];
                o12[pp * 2]     = e * cc - od * ss;
                o12[pp * 2 + 1] = od * cc + e * ss;
            }
            float* cp = C + (size_t)m * N + n0;
            *(float4*)(cp + 0) = *(float4*)&o12[0];
            *(float4*)(cp + 4) = *(float4*)&o12[4];
            *(float4*)(cp + 8) = *(float4*)&o12[8];
        }
    } else if (MODE == 3) {
#pragma unroll
        for (int r = 0; r < 8; r++) {
            float* cp = C + (size_t)(m0 + r) * N + n0;
            *(float4*)(cp + 0) = *(float4*)&acc[r][0];
            *(float4*)(cp + 4) = *(float4*)&acc[r][4];
            *(float4*)(cp + 8) = *(float4*)&acc[r][8];
        }
    } else { // MODE 4
        float bv[12];
#pragma unroll
        for (int c = 0; c < 12; c++) bv[c] = __ldg(&bias[n0 + c]);
#pragma unroll
        for (int r = 0; r < 8; r++) {
            int gr = x_row_of(m0 + r);
            size_t base = (size_t)gr * N + n0;
            float4 x0 = *(const float4*)(xres + base);
            float4 x1 = *(const float4*)(xres + base + 4);
            float4 x2 = *(const float4*)(xres + base + 8);
            float o12[12];
            o12[0]  = acc[r][0]  + bv[0]  + x0.x;
            o12[1]  = acc[r][1]  + bv[1]  + x0.y;
            o12[2]  = acc[r][2]  + bv[2]  + x0.z;
            o12[3]  = acc[r][3]  + bv[3]  + x0.w;
            o12[4]  = acc[r][4]  + bv[4]  + x1.x;
            o12[5]  = acc[r][5]  + bv[5]  + x1.y;
            o12[6]  = acc[r][6]  + bv[6]  + x1.z;
            o12[7]  = acc[r][7]  + bv[7]  + x1.w;
            o12[8]  = acc[r][8]  + bv[8]  + x2.x;
            o12[9]  = acc[r][9]  + bv[9]  + x2.y;
            o12[10] = acc[r][10] + bv[10] + x2.z;
            o12[11] = acc[r][11] + bv[11] + x2.w;
            *(float4*)(C + base)     = *(float4*)&o12[0];
            *(float4*)(C + base + 4) = *(float4*)&o12[4];
            *(float4*)(C + base + 8) = *(float4*)&o12[8];
        }
    }
}

// ---------------- per-sequence retention attention -------------------------
__global__ void __launch_bounds__(256) k_attn(
    const float* __restrict__ Q, const float* __restrict__ Kmat,
    const float* __restrict__ V, float* __restrict__ R)
{
    __shared__ __align__(16) float sKV[SEQ][DH];
    const int q   = blockIdx.x;
    const int tid = threadIdx.x;
    const int n   = tid >> 3;
    const int j   = tid & 7;
    const size_t base = (size_t)q * SEQ * DH;

    for (int i = tid; i < SEQ * DH / 4; i += 256)
        ((float4*)&sKV[0][0])[i] = ((const float4*)(Kmat + base))[i];

    float qr[24];
    const float* qp = Q + base + (size_t)n * DH + j * 24;
#pragma unroll
    for (int dd = 0; dd < 6; dd++)
        *(float4*)&qr[dd * 4] = *(const float4*)(qp + dd * 4);
    __syncthreads();

    float att[SEQ];
#pragma unroll
    for (int m = 0; m < SEQ; m++) {
        float s = 0.0f;
#pragma unroll
        for (int dd = 0; dd < 6; dd++) {
            float4 kv = *(const float4*)&sKV[m][j * 24 + dd * 4];
            s += qr[dd*4+0]*kv.x + qr[dd*4+1]*kv.y + qr[dd*4+2]*kv.z + qr[dd*4+3]*kv.w;
        }
        att[m] = s;
    }
#pragma unroll
    for (int m = 0; m < SEQ; m++) {
#pragma unroll
        for (int o = 1; o < 8; o <<= 1)
            att[m] += __shfl_xor_sync(0xffffffffu, att[m], o);
        att[m] = (n >= m) ? ldexpf(att[m], m - n) : 0.0f;
    }

    __syncthreads();
    for (int i = tid; i < SEQ * DH / 4; i += 256)
        ((float4*)&sKV[0][0])[i] = ((const float4*)(V + base))[i];
    __syncthreads();

    float acc[24];
#pragma unroll
    for (int dd = 0; dd < 24; dd++) acc[dd] = 0.0f;
#pragma unroll
    for (int m = 0; m < SEQ; m++) {
        float a = att[m];
#pragma unroll
        for (int dd = 0; dd < 6; dd++) {
            float4 vv = *(const float4*)&sKV[m][j * 24 + dd * 4];
            acc[dd*4+0] += a * vv.x; acc[dd*4+1] += a * vv.y;
            acc[dd*4+2] += a * vv.z; acc[dd*4+3] += a * vv.w;
        }
    }
    float* rp = R + base + (size_t)n * DH + j * 24;
#pragma unroll
    for (int dd = 0; dd < 6; dd++)
        *(float4*)(rp + dd * 4) = *(const float4*)&acc[dd * 4];
}

// ---------------- launch --------------------------------------------------
extern "C" void kernel_launch(void* const* d_in, const int* in_sizes, int n_in,
                              void* d_out, int out_size)
{
    const float* x    = (const float*)d_in[0];
    const float* W1   = (const float*)d_in[1];
    const float* b1   = (const float*)d_in[2];
    const float* W2   = (const float*)d_in[3];
    const float* b2   = (const float*)d_in[4];
    const float* ln_g = (const float*)d_in[5];
    const float* ln_b = (const float*)d_in[6];
    const float* WQ   = (const float*)d_in[7];
    const float* WK   = (const float*)d_in[8];
    const float* WV   = (const float*)d_in[9];
    float* out = (float*)d_out;

    float* xd = nullptr; cudaGetSymbolAddress((void**)&xd, g_xd);
    float* qb = nullptr; cudaGetSymbolAddress((void**)&qb, g_q);
    float* kb = nullptr; cudaGetSymbolAddress((void**)&kb, g_k);
    float* vb = nullptr; cudaGetSymbolAddress((void**)&vb, g_v);
    float* rb = nullptr; cudaGetSymbolAddress((void**)&rb, g_ret);

    k_tables<<<12, 256>>>();

    // GEMM1 + bias + fused LN: x(gathered) @ W1 -> g_xd  [M=50176, K=768, N=192]
    k_gemm<0><<<dim3(1, MTOT / 128), 256>>>(x, W1, b1, ln_g, ln_b, nullptr, xd, DD, DH);
    // QKV: h @ W{Q,K,V}  [M=50176, K=192, N=192], xPos fused for Q/K
    k_gemm<1><<<dim3(1, MTOT / 128), 256>>>(xd, WQ, nullptr, nullptr, nullptr, nullptr, qb, DH, DH);
    k_gemm<2><<<dim3(1, MTOT / 128), 256>>>(xd, WK, nullptr, nullptr, nullptr, nullptr, kb, DH, DH);
    k_gemm<3><<<dim3(1, MTOT / 128), 256>>>(xd, WV, nullptr, nullptr, nullptr, nullptr, vb, DH, DH);
    k_attn<<<NSEQ, 256>>>(qb, kb, vb, rb);
    // GEMM2: ret @ W2 + b2 + x (residual) -> d_out  [M=50176, K=192, N=768]
    k_gemm<4><<<dim3(DD / 192, MTOT / 128), 256>>>(rb, W2, b2, nullptr, nullptr, x, out, DH, DD);
}

// round 9
// speedup vs baseline: 1.1480x; 1.0892x over previous
#include <cuda_runtime.h>
#include <cstdint>

// ---------------- problem constants ----------------
#define HW   196
#define BB   8
#define SEQ  32
#define DD   768
#define DH   192
#define HALF 96                  // DH/2
#define NSEQ (BB*HW)             // 1568
#define MTOT (NSEQ*SEQ)          // 50176

// ---------------- scratch (__device__ globals) ------------------------------
__device__ float g_xd [MTOT*DH];
__device__ float g_q  [MTOT*DH];
__device__ float g_k  [MTOT*DH];
__device__ float g_v  [MTOT*DH];
__device__ float g_ret[MTOT*DH];

// xPos tables: [t (0..31)][p (0..95)]
__device__ float g_cos_u[SEQ*HALF];
__device__ float g_sin_u[SEQ*HALF];
__device__ float g_cos_d[SEQ*HALF];
__device__ float g_sin_d[SEQ*HALF];

// row m of the logical xr[(b*hw), s, D] maps to this row of x[(hw), b*s, D]
__device__ __forceinline__ int x_row_of(int m) {
    int q  = m >> 5;
    int t  = m & 31;
    int bi = q / HW;
    int hi = q - bi * HW;
    return hi * (BB * SEQ) + bi * SEQ + t;
}

// ---------------- packed f32x2 helpers (sm_100-family PTX) ------------------
__device__ __forceinline__ uint64_t pack_dup(float x) {
    uint64_t r;
    asm("mov.b64 %0, {%1, %1};" : "=l"(r) : "f"(x));
    return r;
}
__device__ __forceinline__ void fma2(uint64_t& d, uint64_t a, uint64_t b) {
    asm("fma.rn.f32x2 %0, %1, %2, %0;" : "+l"(d) : "l"(a), "l"(b));
}
__device__ __forceinline__ float2 unpack2(uint64_t v) {
    float2 f;
    asm("mov.b64 {%0, %1}, %2;" : "=f"(f.x), "=f"(f.y) : "l"(v));
    return f;
}

// ---------------- xPos table precompute (fp64) ------------------------------
__global__ void k_tables() {
    int i = blockIdx.x * blockDim.x + threadIdx.x;
    if (i >= SEQ * HALF) return;
    int t = i / HALF, p = i % HALF;
    double base = (2.0 * p + 0.4 * (double)DH) / (1.4 * (double)DH);
    double sc_u = pow(base, (double)t / 512.0);
    double sc_d = 1.0 / sc_u;
    double invf = pow(10000.0, -(double)p / (double)HALF);
    double ang  = (double)t * invf;
    double s = sin(ang), c = cos(ang);
    g_cos_u[i] = (float)(c * sc_u);
    g_sin_u[i] = (float)(s * sc_u);
    g_cos_d[i] = (float)(c * sc_d);
    g_sin_d[i] = (float)(s * sc_d);
}

// ---------------- tiled SGEMM, packed f32x2, BM=64 BN=192 BK=16 -------------
// 128 threads (2 CTAs/SM), microtile 8 rows x 12 cols. Double-buffered.
// MODE 0: A gathered from x; +bias then fused LayerNorm            -> C
// MODE 1: xPos upscale epilogue                                    -> C
// MODE 2: xPos downscale epilogue                                  -> C
// MODE 3: plain                                                    -> C
// MODE 4: +bias +x residual (gathered rows), gathered store        -> C
template <int MODE>
__global__ void __launch_bounds__(128, 2) k_gemm(
    const float* __restrict__ A, const float* __restrict__ B,
    const float* __restrict__ bias,
    const float* __restrict__ lng, const float* __restrict__ lnb,
    const float* __restrict__ xres,
    float* __restrict__ C, int K, int N)
{
    constexpr int BM = 64, BN = 192, BK = 16;
    constexpr int THREADS = 128;
    constexpr int AMP = 68;

    __shared__ __align__(16) float As[2][BK][AMP];
    __shared__ __align__(16) float Bs[2][BK][BN];

    const int tid = threadIdx.x;
    const int txx = tid & 15;          // N dir: 16 * 12 = 192
    const int tyy = tid >> 4;          // M dir: 8 * 8   = 64
    const int bm  = blockIdx.y * BM;
    const int bn  = blockIdx.x * BN;

    // A: 2 float4 per thread
    int aRow[2], aKq[2];
    const float* aPtr[2];
#pragma unroll
    for (int i = 0; i < 2; i++) {
        int f4 = tid + i * THREADS;
        aRow[i] = f4 >> 2;
        aKq[i]  = f4 & 3;
        int gm  = bm + aRow[i];
        int gr  = (MODE == 0) ? x_row_of(gm) : gm;
        aPtr[i] = A + (size_t)gr * K + aKq[i] * 4;
    }
    // B: 6 float4 per thread (row of 48 float4s)
    int bRow[6], bCol[6];
#pragma unroll
    for (int i = 0; i < 6; i++) {
        int f4 = tid + i * THREADS;
        bRow[i] = f4 / 48;
        bCol[i] = (f4 % 48) * 4;
    }

    // acc2[r][cp] = packed cols {2cp, 2cp+1} of row r
    uint64_t acc2[8][6];
#pragma unroll
    for (int r = 0; r < 8; r++)
#pragma unroll
        for (int cp = 0; cp < 6; cp++) acc2[r][cp] = 0ull;

    float4 aReg[2], bReg[6];

    auto loadG = [&](int k0) {
#pragma unroll
        for (int i = 0; i < 2; i++)
            aReg[i] = *(const float4*)(aPtr[i] + k0);
#pragma unroll
        for (int i = 0; i < 6; i++)
            bReg[i] = *(const float4*)(B + (size_t)(k0 + bRow[i]) * N + bn + bCol[i]);
    };
    auto storeS = [&](int buf) {
#pragma unroll
        for (int i = 0; i < 2; i++) {
            As[buf][aKq[i] * 4 + 0][aRow[i]] = aReg[i].x;
            As[buf][aKq[i] * 4 + 1][aRow[i]] = aReg[i].y;
            As[buf][aKq[i] * 4 + 2][aRow[i]] = aReg[i].z;
            As[buf][aKq[i] * 4 + 3][aRow[i]] = aReg[i].w;
        }
#pragma unroll
        for (int i = 0; i < 6; i++)
            *(float4*)&Bs[buf][bRow[i]][bCol[i]] = bReg[i];
    };
    auto compute = [&](int buf) {
#pragma unroll
        for (int kk = 0; kk < BK; kk++) {
            float a[8];
            *(float4*)&a[0] = *(const float4*)&As[buf][kk][tyy * 8];
            *(float4*)&a[4] = *(const float4*)&As[buf][kk][tyy * 8 + 4];
            uint64_t b2[6];
            const uint64_t* bp = (const uint64_t*)&Bs[buf][kk][txx * 12];
#pragma unroll
            for (int i = 0; i < 6; i++) b2[i] = bp[i];
            uint64_t a2[8];
#pragma unroll
            for (int r = 0; r < 8; r++) a2[r] = pack_dup(a[r]);
#pragma unroll
            for (int r = 0; r < 8; r++)
#pragma unroll
                for (int cp = 0; cp < 6; cp++)
                    fma2(acc2[r][cp], a2[r], b2[cp]);
        }
    };

    loadG(0);
    storeS(0);
    __syncthreads();
    int cur = 0;
    for (int k0 = BK; k0 < K; k0 += BK) {
        loadG(k0);
        compute(cur);
        storeS(cur ^ 1);
        __syncthreads();
        cur ^= 1;
    }
    compute(cur);

    // unpack
    float acc[8][12];
#pragma unroll
    for (int r = 0; r < 8; r++)
#pragma unroll
        for (int cp = 0; cp < 6; cp++) {
            float2 t = unpack2(acc2[r][cp]);
            acc[r][2 * cp]     = t.x;
            acc[r][2 * cp + 1] = t.y;
        }

    const int m0 = bm + tyy * 8;
    const int n0 = bn + txx * 12;

    if (MODE == 0) {
        // +bias, then LayerNorm across the 16 txx lanes (full 192-col row)
        float bv[12];
#pragma unroll
        for (int c = 0; c < 12; c++) bv[c] = __ldg(&bias[n0 + c]);
        float gv[12], be[12];
#pragma unroll
        for (int c = 0; c < 12; c++) { gv[c] = __ldg(&lng[n0 + c]); be[c] = __ldg(&lnb[n0 + c]); }
#pragma unroll
        for (int r = 0; r < 8; r++) {
            float s1 = 0.f, s2 = 0.f;
#pragma unroll
            for (int c = 0; c < 12; c++) {
                float v = acc[r][c] + bv[c];
                acc[r][c] = v;
                s1 += v; s2 += v * v;
            }
#pragma unroll
            for (int o = 1; o < 16; o <<= 1) {
                s1 += __shfl_xor_sync(0xffffffffu, s1, o);
                s2 += __shfl_xor_sync(0xffffffffu, s2, o);
            }
            float mu  = s1 * (1.0f / 192.0f);
            float inv = rsqrtf(s2 * (1.0f / 192.0f) - mu * mu + 1e-5f);
            float o12[12];
#pragma unroll
            for (int c = 0; c < 12; c++)
                o12[c] = (acc[r][c] - mu) * inv * gv[c] + be[c];
            float* cp = C + (size_t)(m0 + r) * N + n0;
            *(float4*)(cp + 0) = *(float4*)&o12[0];
            *(float4*)(cp + 4) = *(float4*)&o12[4];
            *(float4*)(cp + 8) = *(float4*)&o12[8];
        }
    } else if (MODE == 1 || MODE == 2) {
        const float* ct = (MODE == 1) ? g_cos_u : g_cos_d;
        const float* st = (MODE == 1) ? g_sin_u : g_sin_d;
        const int p0 = n0 >> 1;
#pragma unroll
        for (int r = 0; r < 8; r++) {
            int m = m0 + r;
            int t = m & 31;
            float o12[12];
#pragma unroll
            for (int pp = 0; pp < 6; pp++) {
                float cc = ct[t * HALF + p0 + pp];
                float ss = st[t * HALF + p0 + pp];
                float e = acc[r][pp * 2], od = acc[r][pp * 2 + 1];
                o12[pp * 2]     = e * cc - od * ss;
                o12[pp * 2 + 1] = od * cc + e * ss;
            }
            float* cp = C + (size_t)m * N + n0;
            *(float4*)(cp + 0) = *(float4*)&o12[0];
            *(float4*)(cp + 4) = *(float4*)&o12[4];
            *(float4*)(cp + 8) = *(float4*)&o12[8];
        }
    } else if (MODE == 3) {
#pragma unroll
        for (int r = 0; r < 8; r++) {
            float* cp = C + (size_t)(m0 + r) * N + n0;
            *(float4*)(cp + 0) = *(float4*)&acc[r][0];
            *(float4*)(cp + 4) = *(float4*)&acc[r][4];
            *(float4*)(cp + 8) = *(float4*)&acc[r][8];
        }
    } else { // MODE 4
        float bv[12];
#pragma unroll
        for (int c = 0; c < 12; c++) bv[c] = __ldg(&bias[n0 + c]);
#pragma unroll
        for (int r = 0; r < 8; r++) {
            int gr = x_row_of(m0 + r);
            size_t base = (size_t)gr * N + n0;
            float4 x0 = *(const float4*)(xres + base);
            float4 x1 = *(const float4*)(xres + base + 4);
            float4 x2 = *(const float4*)(xres + base + 8);
            float o12[12];
            o12[0]  = acc[r][0]  + bv[0]  + x0.x;
            o12[1]  = acc[r][1]  + bv[1]  + x0.y;
            o12[2]  = acc[r][2]  + bv[2]  + x0.z;
            o12[3]  = acc[r][3]  + bv[3]  + x0.w;
            o12[4]  = acc[r][4]  + bv[4]  + x1.x;
            o12[5]  = acc[r][5]  + bv[5]  + x1.y;
            o12[6]  = acc[r][6]  + bv[6]  + x1.z;
            o12[7]  = acc[r][7]  + bv[7]  + x1.w;
            o12[8]  = acc[r][8]  + bv[8]  + x2.x;
            o12[9]  = acc[r][9]  + bv[9]  + x2.y;
            o12[10] = acc[r][10] + bv[10] + x2.z;
            o12[11] = acc[r][11] + bv[11] + x2.w;
            *(float4*)(C + base)     = *(float4*)&o12[0];
            *(float4*)(C + base + 4) = *(float4*)&o12[4];
            *(float4*)(C + base + 8) = *(float4*)&o12[8];
        }
    }
}

// ---------------- per-sequence retention attention -------------------------
__global__ void __launch_bounds__(256) k_attn(
    const float* __restrict__ Q, const float* __restrict__ Kmat,
    const float* __restrict__ V, float* __restrict__ R)
{
    __shared__ __align__(16) float sKV[SEQ][DH];
    const int q   = blockIdx.x;
    const int tid = threadIdx.x;
    const int n   = tid >> 3;
    const int j   = tid & 7;
    const size_t base = (size_t)q * SEQ * DH;

    for (int i = tid; i < SEQ * DH / 4; i += 256)
        ((float4*)&sKV[0][0])[i] = ((const float4*)(Kmat + base))[i];

    float qr[24];
    const float* qp = Q + base + (size_t)n * DH + j * 24;
#pragma unroll
    for (int dd = 0; dd < 6; dd++)
        *(float4*)&qr[dd * 4] = *(const float4*)(qp + dd * 4);
    __syncthreads();

    float att[SEQ];
#pragma unroll
    for (int m = 0; m < SEQ; m++) {
        float s = 0.0f;
#pragma unroll
        for (int dd = 0; dd < 6; dd++) {
            float4 kv = *(const float4*)&sKV[m][j * 24 + dd * 4];
            s += qr[dd*4+0]*kv.x + qr[dd*4+1]*kv.y + qr[dd*4+2]*kv.z + qr[dd*4+3]*kv.w;
        }
        att[m] = s;
    }
#pragma unroll
    for (int m = 0; m < SEQ; m++) {
#pragma unroll
        for (int o = 1; o < 8; o <<= 1)
            att[m] += __shfl_xor_sync(0xffffffffu, att[m], o);
        att[m] = (n >= m) ? ldexpf(att[m], m - n) : 0.0f;
    }

    __syncthreads();
    for (int i = tid; i < SEQ * DH / 4; i += 256)
        ((float4*)&sKV[0][0])[i] = ((const float4*)(V + base))[i];
    __syncthreads();

    float acc[24];
#pragma unroll
    for (int dd = 0; dd < 24; dd++) acc[dd] = 0.0f;
#pragma unroll
    for (int m = 0; m < SEQ; m++) {
        float a = att[m];
#pragma unroll
        for (int dd = 0; dd < 6; dd++) {
            float4 vv = *(const float4*)&sKV[m][j * 24 + dd * 4];
            acc[dd*4+0] += a * vv.x; acc[dd*4+1] += a * vv.y;
            acc[dd*4+2] += a * vv.z; acc[dd*4+3] += a * vv.w;
        }
    }
    float* rp = R + base + (size_t)n * DH + j * 24;
#pragma unroll
    for (int dd = 0; dd < 6; dd++)
        *(float4*)(rp + dd * 4) = *(const float4*)&acc[dd * 4];
}

// ---------------- launch --------------------------------------------------
extern "C" void kernel_launch(void* const* d_in, const int* in_sizes, int n_in,
                              void* d_out, int out_size)
{
    const float* x    = (const float*)d_in[0];
    const float* W1   = (const float*)d_in[1];
    const float* b1   = (const float*)d_in[2];
    const float* W2   = (const float*)d_in[3];
    const float* b2   = (const float*)d_in[4];
    const float* ln_g = (const float*)d_in[5];
    const float* ln_b = (const float*)d_in[6];
    const float* WQ   = (const float*)d_in[7];
    const float* WK   = (const float*)d_in[8];
    const float* WV   = (const float*)d_in[9];
    float* out = (float*)d_out;

    float* xd = nullptr; cudaGetSymbolAddress((void**)&xd, g_xd);
    float* qb = nullptr; cudaGetSymbolAddress((void**)&qb, g_q);
    float* kb = nullptr; cudaGetSymbolAddress((void**)&kb, g_k);
    float* vb = nullptr; cudaGetSymbolAddress((void**)&vb, g_v);
    float* rb = nullptr; cudaGetSymbolAddress((void**)&rb, g_ret);

    k_tables<<<12, 256>>>();

    // GEMM1 + bias + fused LN: x(gathered) @ W1 -> g_xd  [M=50176, K=768, N=192]
    k_gemm<0><<<dim3(1, MTOT / 64), 128>>>(x, W1, b1, ln_g, ln_b, nullptr, xd, DD, DH);
    // QKV: h @ W{Q,K,V}  [M=50176, K=192, N=192], xPos fused for Q/K
    k_gemm<1><<<dim3(1, MTOT / 64), 128>>>(xd, WQ, nullptr, nullptr, nullptr, nullptr, qb, DH, DH);
    k_gemm<2><<<dim3(1, MTOT / 64), 128>>>(xd, WK, nullptr, nullptr, nullptr, nullptr, kb, DH, DH);
    k_gemm<3><<<dim3(1, MTOT / 64), 128>>>(xd, WV, nullptr, nullptr, nullptr, nullptr, vb, DH, DH);
    k_attn<<<NSEQ, 256>>>(qb, kb, vb, rb);
    // GEMM2: ret @ W2 + b2 + x (residual) -> d_out  [M=50176, K=192, N=768]
    k_gemm<4><<<dim3(DD / 192, MTOT / 64), 128>>>(rb, W2, b2, nullptr, nullptr, x, out, DH, DD);
}

// round 10
// speedup vs baseline: 1.1596x; 1.0101x over previous
#include <cuda_runtime.h>
#include <cstdint>

// ---------------- problem constants ----------------
#define HW   196
#define BB   8
#define SEQ  32
#define DD   768
#define DH   192
#define HALF 96                  // DH/2
#define NSEQ (BB*HW)             // 1568
#define MTOT (NSEQ*SEQ)          // 50176

// ---------------- scratch (__device__ globals) ------------------------------
__device__ float g_xd [MTOT*DH];
__device__ float g_q  [MTOT*DH];
__device__ float g_k  [MTOT*DH];
__device__ float g_v  [MTOT*DH];
__device__ float g_ret[MTOT*DH];

// xPos tables: [t (0..31)][p (0..95)]
__device__ float g_cos_u[SEQ*HALF];
__device__ float g_sin_u[SEQ*HALF];
__device__ float g_cos_d[SEQ*HALF];
__device__ float g_sin_d[SEQ*HALF];

// row m of the logical xr[(b*hw), s, D] maps to this row of x[(hw), b*s, D]
__device__ __forceinline__ int x_row_of(int m) {
    int q  = m >> 5;
    int t  = m & 31;
    int bi = q / HW;
    int hi = q - bi * HW;
    return hi * (BB * SEQ) + bi * SEQ + t;
}

// ---------------- packed f32x2 + async-copy helpers --------------------------
__device__ __forceinline__ uint64_t pack_dup(float x) {
    uint64_t r;
    asm("mov.b64 %0, {%1, %1};" : "=l"(r) : "f"(x));
    return r;
}
__device__ __forceinline__ void fma2(uint64_t& d, uint64_t a, uint64_t b) {
    asm("fma.rn.f32x2 %0, %1, %2, %0;" : "+l"(d) : "l"(a), "l"(b));
}
__device__ __forceinline__ float2 unpack2(uint64_t v) {
    float2 f;
    asm("mov.b64 {%0, %1}, %2;" : "=f"(f.x), "=f"(f.y) : "l"(v));
    return f;
}
__device__ __forceinline__ void cpasync16(uint32_t s, const void* g) {
    asm volatile("cp.async.ca.shared.global [%0], [%1], 16;" :: "r"(s), "l"(g) : "memory");
}
#define CP_COMMIT() asm volatile("cp.async.commit_group;" ::: "memory")
#define CP_WAIT0()  asm volatile("cp.async.wait_group 0;" ::: "memory")

// ---------------- xPos table precompute (fp64) ------------------------------
__global__ void k_tables() {
    int i = blockIdx.x * blockDim.x + threadIdx.x;
    if (i >= SEQ * HALF) return;
    int t = i / HALF, p = i % HALF;
    double base = (2.0 * p + 0.4 * (double)DH) / (1.4 * (double)DH);
    double sc_u = pow(base, (double)t / 512.0);
    double sc_d = 1.0 / sc_u;
    double invf = pow(10000.0, -(double)p / (double)HALF);
    double ang  = (double)t * invf;
    double s = sin(ang), c = cos(ang);
    g_cos_u[i] = (float)(c * sc_u);
    g_sin_u[i] = (float)(s * sc_u);
    g_cos_d[i] = (float)(c * sc_d);
    g_sin_d[i] = (float)(s * sc_d);
}

// ---------------- tiled SGEMM, packed f32x2, BM=64 BN=192 BK=16 -------------
// 128 threads, 3 CTAs/SM target. Microtile 8x12. B via cp.async, A via LDG+STS.
// MODE 0: A gathered from x; +bias then fused LayerNorm            -> C
// MODE 1: xPos upscale epilogue                                    -> C
// MODE 2: xPos downscale epilogue                                  -> C
// MODE 3: plain                                                    -> C
// MODE 4: +bias +x residual (gathered rows), gathered store        -> C
template <int MODE>
__global__ void __launch_bounds__(128, 3) k_gemm(
    const float* __restrict__ A, const float* __restrict__ B,
    const float* __restrict__ bias,
    const float* __restrict__ lng, const float* __restrict__ lnb,
    const float* __restrict__ xres,
    float* __restrict__ C, int K, int N)
{
    constexpr int BM = 64, BN = 192, BK = 16;
    constexpr int THREADS = 128;
    constexpr int AMP = 68;

    __shared__ __align__(16) float As[2][BK][AMP];
    __shared__ __align__(16) float Bs[2][BK][BN];

    const int tid = threadIdx.x;
    const int txx = tid & 15;          // N dir: 16 * 12 = 192
    const int tyy = tid >> 4;          // M dir: 8 * 8   = 64
    const int bm  = blockIdx.y * BM;
    const int bn  = blockIdx.x * BN;

    // A: 2 float4 per thread
    int aRow[2], aKq[2];
    const float* aPtr[2];
#pragma unroll
    for (int i = 0; i < 2; i++) {
        int f4 = tid + i * THREADS;
        aRow[i] = f4 >> 2;
        aKq[i]  = f4 & 3;
        int gm  = bm + aRow[i];
        int gr  = (MODE == 0) ? x_row_of(gm) : gm;
        aPtr[i] = A + (size_t)gr * K + aKq[i] * 4;
    }
    // B: 6 cp.async float4 per thread (row of 48 float4s)
    int bRow[6], bCol[6];
#pragma unroll
    for (int i = 0; i < 6; i++) {
        int f4 = tid + i * THREADS;
        bRow[i] = f4 / 48;
        bCol[i] = (f4 % 48) * 4;
    }

    uint64_t acc2[8][6];
#pragma unroll
    for (int r = 0; r < 8; r++)
#pragma unroll
        for (int cp = 0; cp < 6; cp++) acc2[r][cp] = 0ull;

    float4 aReg[2];

    auto loadA = [&](int k0) {
#pragma unroll
        for (int i = 0; i < 2; i++)
            aReg[i] = *(const float4*)(aPtr[i] + k0);
    };
    auto issueB = [&](int k0, int buf) {
#pragma unroll
        for (int i = 0; i < 6; i++) {
            uint32_t dst = (uint32_t)__cvta_generic_to_shared(&Bs[buf][bRow[i]][bCol[i]]);
            cpasync16(dst, B + (size_t)(k0 + bRow[i]) * N + bn + bCol[i]);
        }
        CP_COMMIT();
    };
    auto storeA = [&](int buf) {
#pragma unroll
        for (int i = 0; i < 2; i++) {
            As[buf][aKq[i] * 4 + 0][aRow[i]] = aReg[i].x;
            As[buf][aKq[i] * 4 + 1][aRow[i]] = aReg[i].y;
            As[buf][aKq[i] * 4 + 2][aRow[i]] = aReg[i].z;
            As[buf][aKq[i] * 4 + 3][aRow[i]] = aReg[i].w;
        }
    };
    auto compute = [&](int buf) {
#pragma unroll
        for (int kk = 0; kk < BK; kk++) {
            float a[8];
            *(float4*)&a[0] = *(const float4*)&As[buf][kk][tyy * 8];
            *(float4*)&a[4] = *(const float4*)&As[buf][kk][tyy * 8 + 4];
            uint64_t b2[6];
            const uint64_t* bp = (const uint64_t*)&Bs[buf][kk][txx * 12];
#pragma unroll
            for (int i = 0; i < 6; i++) b2[i] = bp[i];
            uint64_t a2[8];
#pragma unroll
            for (int r = 0; r < 8; r++) a2[r] = pack_dup(a[r]);
#pragma unroll
            for (int r = 0; r < 8; r++)
#pragma unroll
                for (int cp = 0; cp < 6; cp++)
                    fma2(acc2[r][cp], a2[r], b2[cp]);
        }
    };

    // prologue: fill buffer 0
    loadA(0);
    issueB(0, 0);
    storeA(0);
    CP_WAIT0();
    __syncthreads();

    int cur = 0;
    for (int k0 = BK; k0 < K; k0 += BK) {
        loadA(k0);
        issueB(k0, cur ^ 1);
        compute(cur);
        storeA(cur ^ 1);
        CP_WAIT0();
        __syncthreads();
        cur ^= 1;
    }
    compute(cur);

    // unpack
    float acc[8][12];
#pragma unroll
    for (int r = 0; r < 8; r++)
#pragma unroll
        for (int cp = 0; cp < 6; cp++) {
            float2 t = unpack2(acc2[r][cp]);
            acc[r][2 * cp]     = t.x;
            acc[r][2 * cp + 1] = t.y;
        }

    const int m0 = bm + tyy * 8;
    const int n0 = bn + txx * 12;

    if (MODE == 0) {
        float bv[12];
#pragma unroll
        for (int c = 0; c < 12; c++) bv[c] = __ldg(&bias[n0 + c]);
        float gv[12], be[12];
#pragma unroll
        for (int c = 0; c < 12; c++) { gv[c] = __ldg(&lng[n0 + c]); be[c] = __ldg(&lnb[n0 + c]); }
#pragma unroll
        for (int r = 0; r < 8; r++) {
            float s1 = 0.f, s2 = 0.f;
#pragma unroll
            for (int c = 0; c < 12; c++) {
                float v = acc[r][c] + bv[c];
                acc[r][c] = v;
                s1 += v; s2 += v * v;
            }
#pragma unroll
            for (int o = 1; o < 16; o <<= 1) {
                s1 += __shfl_xor_sync(0xffffffffu, s1, o);
                s2 += __shfl_xor_sync(0xffffffffu, s2, o);
            }
            float mu  = s1 * (1.0f / 192.0f);
            float inv = rsqrtf(s2 * (1.0f / 192.0f) - mu * mu + 1e-5f);
            float o12[12];
#pragma unroll
            for (int c = 0; c < 12; c++)
                o12[c] = (acc[r][c] - mu) * inv * gv[c] + be[c];
            float* cp = C + (size_t)(m0 + r) * N + n0;
            *(float4*)(cp + 0) = *(float4*)&o12[0];
            *(float4*)(cp + 4) = *(float4*)&o12[4];
            *(float4*)(cp + 8) = *(float4*)&o12[8];
        }
    } else if (MODE == 1 || MODE == 2) {
        const float* ct = (MODE == 1) ? g_cos_u : g_cos_d;
        const float* st = (MODE == 1) ? g_sin_u : g_sin_d;
        const int p0 = n0 >> 1;
#pragma unroll
        for (int r = 0; r < 8; r++) {
            int m = m0 + r;
            int t = m & 31;
            float o12[12];
#pragma unroll
            for (int pp = 0; pp < 6; pp++) {
                float cc = ct[t * HALF + p0 + pp];
                float ss = st[t * HALF + p0 + pp];
                float e = acc[r][pp * 2], od = acc[r][pp * 2 + 1];
                o12[pp * 2]     = e * cc - od * ss;
                o12[pp * 2 + 1] = od * cc + e * ss;
            }
            float* cp = C + (size_t)m * N + n0;
            *(float4*)(cp + 0) = *(float4*)&o12[0];
            *(float4*)(cp + 4) = *(float4*)&o12[4];
            *(float4*)(cp + 8) = *(float4*)&o12[8];
        }
    } else if (MODE == 3) {
#pragma unroll
        for (int r = 0; r < 8; r++) {
            float* cp = C + (size_t)(m0 + r) * N + n0;
            *(float4*)(cp + 0) = *(float4*)&acc[r][0];
            *(float4*)(cp + 4) = *(float4*)&acc[r][4];
            *(float4*)(cp + 8) = *(float4*)&acc[r][8];
        }
    } else { // MODE 4
        float bv[12];
#pragma unroll
        for (int c = 0; c < 12; c++) bv[c] = __ldg(&bias[n0 + c]);
#pragma unroll
        for (int r = 0; r < 8; r++) {
            int gr = x_row_of(m0 + r);
            size_t base = (size_t)gr * N + n0;
            float4 x0 = *(const float4*)(xres + base);
            float4 x1 = *(const float4*)(xres + base + 4);
            float4 x2 = *(const float4*)(xres + base + 8);
            float o12[12];
            o12[0]  = acc[r][0]  + bv[0]  + x0.x;
            o12[1]  = acc[r][1]  + bv[1]  + x0.y;
            o12[2]  = acc[r][2]  + bv[2]  + x0.z;
            o12[3]  = acc[r][3]  + bv[3]  + x0.w;
            o12[4]  = acc[r][4]  + bv[4]  + x1.x;
            o12[5]  = acc[r][5]  + bv[5]  + x1.y;
            o12[6]  = acc[r][6]  + bv[6]  + x1.z;
            o12[7]  = acc[r][7]  + bv[7]  + x1.w;
            o12[8]  = acc[r][8]  + bv[8]  + x2.x;
            o12[9]  = acc[r][9]  + bv[9]  + x2.y;
            o12[10] = acc[r][10] + bv[10] + x2.z;
            o12[11] = acc[r][11] + bv[11] + x2.w;
            *(float4*)(C + base)     = *(float4*)&o12[0];
            *(float4*)(C + base + 4) = *(float4*)&o12[4];
            *(float4*)(C + base + 8) = *(float4*)&o12[8];
        }
    }
}

// ---------------- per-sequence retention attention -------------------------
__global__ void __launch_bounds__(256) k_attn(
    const float* __restrict__ Q, const float* __restrict__ Kmat,
    const float* __restrict__ V, float* __restrict__ R)
{
    __shared__ __align__(16) float sKV[SEQ][DH];
    const int q   = blockIdx.x;
    const int tid = threadIdx.x;
    const int n   = tid >> 3;
    const int j   = tid & 7;
    const size_t base = (size_t)q * SEQ * DH;

    for (int i = tid; i < SEQ * DH / 4; i += 256)
        ((float4*)&sKV[0][0])[i] = ((const float4*)(Kmat + base))[i];

    float qr[24];
    const float* qp = Q + base + (size_t)n * DH + j * 24;
#pragma unroll
    for (int dd = 0; dd < 6; dd++)
        *(float4*)&qr[dd * 4] = *(const float4*)(qp + dd * 4);
    __syncthreads();

    float att[SEQ];
#pragma unroll
    for (int m = 0; m < SEQ; m++) {
        float s = 0.0f;
#pragma unroll
        for (int dd = 0; dd < 6; dd++) {
            float4 kv = *(const float4*)&sKV[m][j * 24 + dd * 4];
            s += qr[dd*4+0]*kv.x + qr[dd*4+1]*kv.y + qr[dd*4+2]*kv.z + qr[dd*4+3]*kv.w;
        }
        att[m] = s;
    }
#pragma unroll
    for (int m = 0; m < SEQ; m++) {
#pragma unroll
        for (int o = 1; o < 8; o <<= 1)
            att[m] += __shfl_xor_sync(0xffffffffu, att[m], o);
        att[m] = (n >= m) ? ldexpf(att[m], m - n) : 0.0f;
    }

    __syncthreads();
    for (int i = tid; i < SEQ * DH / 4; i += 256)
        ((float4*)&sKV[0][0])[i] = ((const float4*)(V + base))[i];
    __syncthreads();

    float acc[24];
#pragma unroll
    for (int dd = 0; dd < 24; dd++) acc[dd] = 0.0f;
#pragma unroll
    for (int m = 0; m < SEQ; m++) {
        float a = att[m];
#pragma unroll
        for (int dd = 0; dd < 6; dd++) {
            float4 vv = *(const float4*)&sKV[m][j * 24 + dd * 4];
            acc[dd*4+0] += a * vv.x; acc[dd*4+1] += a * vv.y;
            acc[dd*4+2] += a * vv.z; acc[dd*4+3] += a * vv.w;
        }
    }
    float* rp = R + base + (size_t)n * DH + j * 24;
#pragma unroll
    for (int dd = 0; dd < 6; dd++)
        *(float4*)(rp + dd * 4) = *(const float4*)&acc[dd * 4];
}

// ---------------- launch --------------------------------------------------
extern "C" void kernel_launch(void* const* d_in, const int* in_sizes, int n_in,
                              void* d_out, int out_size)
{
    const float* x    = (const float*)d_in[0];
    const float* W1   = (const float*)d_in[1];
    const float* b1   = (const float*)d_in[2];
    const float* W2   = (const float*)d_in[3];
    const float* b2   = (const float*)d_in[4];
    const float* ln_g = (const float*)d_in[5];
    const float* ln_b = (const float*)d_in[6];
    const float* WQ   = (const float*)d_in[7];
    const float* WK   = (const float*)d_in[8];
    const float* WV   = (const float*)d_in[9];
    float* out = (float*)d_out;

    float* xd = nullptr; cudaGetSymbolAddress((void**)&xd, g_xd);
    float* qb = nullptr; cudaGetSymbolAddress((void**)&qb, g_q);
    float* kb = nullptr; cudaGetSymbolAddress((void**)&kb, g_k);
    float* vb = nullptr; cudaGetSymbolAddress((void**)&vb, g_v);
    float* rb = nullptr; cudaGetSymbolAddress((void**)&rb, g_ret);

    k_tables<<<12, 256>>>();

    // GEMM1 + bias + fused LN: x(gathered) @ W1 -> g_xd  [M=50176, K=768, N=192]
    k_gemm<0><<<dim3(1, MTOT / 64), 128>>>(x, W1, b1, ln_g, ln_b, nullptr, xd, DD, DH);
    // QKV: h @ W{Q,K,V}  [M=50176, K=192, N=192], xPos fused for Q/K
    k_gemm<1><<<dim3(1, MTOT / 64), 128>>>(xd, WQ, nullptr, nullptr, nullptr, nullptr, qb, DH, DH);
    k_gemm<2><<<dim3(1, MTOT / 64), 128>>>(xd, WK, nullptr, nullptr, nullptr, nullptr, kb, DH, DH);
    k_gemm<3><<<dim3(1, MTOT / 64), 128>>>(xd, WV, nullptr, nullptr, nullptr, nullptr, vb, DH, DH);
    k_attn<<<NSEQ, 256>>>(qb, kb, vb, rb);
    // GEMM2: ret @ W2 + b2 + x (residual) -> d_out  [M=50176, K=192, N=768]
    k_gemm<4><<<dim3(DD / 192, MTOT / 64), 128>>>(rb, W2, b2, nullptr, nullptr, x, out, DH, DD);
}

// round 11
// speedup vs baseline: 1.1750x; 1.0133x over previous
#include <cuda_runtime.h>
#include <cstdint>

// ---------------- problem constants ----------------
#define HW   196
#define BB   8
#define SEQ  32
#define DD   768
#define DH   192
#define HALF 96                  // DH/2
#define NSEQ (BB*HW)             // 1568
#define MTOT (NSEQ*SEQ)          // 50176

// ---------------- scratch (__device__ globals) ------------------------------
__device__ float g_xd [MTOT*DH];
__device__ float g_q  [MTOT*DH];
__device__ float g_k  [MTOT*DH];
__device__ float g_v  [MTOT*DH];
__device__ float g_ret[MTOT*DH];

// tf32-split weights, natural [K][N] layout (elementwise split, no transpose)
__device__ float g_w1h[DD*DH], g_w1l[DD*DH];
__device__ float g_wqh[DH*DH], g_wql[DH*DH];
__device__ float g_wkh[DH*DH], g_wkl[DH*DH];
__device__ float g_wvh[DH*DH], g_wvl[DH*DH];
__device__ float g_w2h[DH*DD], g_w2l[DH*DD];

// xPos tables: [t (0..31)][p (0..95)]
__device__ float g_cos_u[SEQ*HALF];
__device__ float g_sin_u[SEQ*HALF];
__device__ float g_cos_d[SEQ*HALF];
__device__ float g_sin_d[SEQ*HALF];

// row m of the logical xr[(b*hw), s, D] maps to this row of x[(hw), b*s, D]
__device__ __forceinline__ int x_row_of(int m) {
    int q  = m >> 5;
    int t  = m & 31;
    int bi = q / HW;
    int hi = q - bi * HW;
    return hi * (BB * SEQ) + bi * SEQ + t;
}

// ---------------- helpers ----------------------------------------------------
__device__ __forceinline__ float f2tf32(float x) {
    uint32_t u;
    asm("cvt.rna.tf32.f32 %0, %1;" : "=r"(u) : "f"(x));
    return __uint_as_float(u);
}
__device__ __forceinline__ void cpasync16(uint32_t s, const void* g) {
    asm volatile("cp.async.ca.shared.global [%0], [%1], 16;" :: "r"(s), "l"(g) : "memory");
}
#define CP_COMMIT() asm volatile("cp.async.commit_group;" ::: "memory")
#define CP_WAIT0()  asm volatile("cp.async.wait_group 0;" ::: "memory")

// m16n8k8 tf32 MMA: D += A*B (accumulate in place)
__device__ __forceinline__ void mma8(float* d, const uint32_t* a, uint32_t b0, uint32_t b1) {
    asm volatile(
        "mma.sync.aligned.m16n8k8.row.col.f32.tf32.tf32.f32 "
        "{%0,%1,%2,%3}, {%4,%5,%6,%7}, {%8,%9}, {%0,%1,%2,%3};"
        : "+f"(d[0]), "+f"(d[1]), "+f"(d[2]), "+f"(d[3])
        : "r"(a[0]), "r"(a[1]), "r"(a[2]), "r"(a[3]), "r"(b0), "r"(b1));
}

// ---------------- prep: weight tf32 split + xPos tables ---------------------
__device__ __forceinline__ void w_split(const float* __restrict__ W,
                                        float* __restrict__ Wh, float* __restrict__ Wl, int idx) {
    float v = W[idx];
    float h = f2tf32(v);
    Wh[idx] = h;
    Wl[idx] = f2tf32(v - h);
}

__global__ void k_prep(const float* __restrict__ W1, const float* __restrict__ WQ,
                       const float* __restrict__ WK, const float* __restrict__ WV,
                       const float* __restrict__ W2) {
    int idx = blockIdx.x * blockDim.x + threadIdx.x;
    if (idx < DD*DH) { w_split(W1, g_w1h, g_w1l, idx); return; }
    idx -= DD*DH;
    if (idx < DH*DH) { w_split(WQ, g_wqh, g_wql, idx); return; }
    idx -= DH*DH;
    if (idx < DH*DH) { w_split(WK, g_wkh, g_wkl, idx); return; }
    idx -= DH*DH;
    if (idx < DH*DH) { w_split(WV, g_wvh, g_wvl, idx); return; }
    idx -= DH*DH;
    if (idx < DH*DD) { w_split(W2, g_w2h, g_w2l, idx); return; }
    idx -= DH*DD;
    if (idx < SEQ*HALF) {
        int t = idx / HALF, p = idx % HALF;
        double base = (2.0 * p + 0.4 * (double)DH) / (1.4 * (double)DH);
        double sc_u = pow(base, (double)t / 512.0);
        double sc_d = 1.0 / sc_u;
        double invf = pow(10000.0, -(double)p / (double)HALF);
        double ang  = (double)t * invf;
        double s = sin(ang), c = cos(ang);
        g_cos_u[idx] = (float)(c * sc_u);
        g_sin_u[idx] = (float)(s * sc_u);
        g_cos_d[idx] = (float)(c * sc_d);
        g_sin_d[idx] = (float)(s * sc_d);
    }
}

// ---------------- 3xTF32 mma.sync GEMM, BM=64 BN=192 BK=16 ------------------
// 128 threads = 4 warps; warp w -> rows w*16..w*16+15, all 192 cols (24 n-tiles).
// A split hi/lo on the fly (LDG+cvt+STS); B pre-split, loaded via cp.async.
// MODE 0: A gathered from x; +bias then fused LayerNorm            -> C
// MODE 1: xPos upscale epilogue                                    -> C
// MODE 2: xPos downscale epilogue                                  -> C
// MODE 3: plain                                                    -> C
// MODE 4: +bias +x residual (gathered rows), gathered store        -> C
//
// smem (floats): AH[2][64][20], AL[2][64][20], BH[2][16][200], BL[2][16][200]
#define AP 20
#define BP 200
#define A_BUF (64*AP)            // 1280
#define B_BUF (16*BP)            // 3200
#define SMEM_FLOATS (4*A_BUF + 4*B_BUF)   // 17920 -> 71680 B

template <int MODE>
__global__ void __launch_bounds__(128) k_mma(
    const float* __restrict__ A,
    const float* __restrict__ Bhi, const float* __restrict__ Blo,
    const float* __restrict__ bias,
    const float* __restrict__ lng, const float* __restrict__ lnb,
    const float* __restrict__ xres,
    float* __restrict__ C, int K, int N)
{
    extern __shared__ float sm[];
    float* AH = sm;
    float* AL = sm + 2*A_BUF;
    float* BH = sm + 4*A_BUF;
    float* BL = sm + 4*A_BUF + 2*B_BUF;

    const int tid  = threadIdx.x;
    const int w    = tid >> 5;
    const int lane = tid & 31;
    const int g    = lane >> 2;       // group id 0..7
    const int tg   = lane & 3;        // thread in group 0..3
    const int bm   = blockIdx.y * 64;
    const int bn   = blockIdx.x * 192;
    const int m0w  = w * 16;

    // A loads: 2 float4 slots per thread
    int aRow[2], aKq[2];
    const float* aPtr[2];
#pragma unroll
    for (int i = 0; i < 2; i++) {
        int f4 = tid + i * 128;
        aRow[i] = f4 >> 2;
        aKq[i]  = f4 & 3;
        int gm  = bm + aRow[i];
        int gr  = (MODE == 0) ? x_row_of(gm) : gm;
        aPtr[i] = A + (size_t)gr * K + aKq[i] * 4;
    }
    // B cp.async: 6 float4 slots per thread per array
    int bRow[6], bCol[6];
#pragma unroll
    for (int i = 0; i < 6; i++) {
        int f4 = tid + i * 128;
        bRow[i] = f4 / 48;
        bCol[i] = (f4 % 48) * 4;
    }

    float acc[24][4];
#pragma unroll
    for (int nt = 0; nt < 24; nt++)
#pragma unroll
        for (int e = 0; e < 4; e++) acc[nt][e] = 0.0f;

    float4 aReg[2];

    auto loadA = [&](int k0) {
#pragma unroll
        for (int i = 0; i < 2; i++)
            aReg[i] = *(const float4*)(aPtr[i] + k0);
    };
    auto storeA = [&](int buf) {
#pragma unroll
        for (int i = 0; i < 2; i++) {
            float4 v = aReg[i];
            float4 h, l;
            h.x = f2tf32(v.x); h.y = f2tf32(v.y); h.z = f2tf32(v.z); h.w = f2tf32(v.w);
            l.x = f2tf32(v.x - h.x); l.y = f2tf32(v.y - h.y);
            l.z = f2tf32(v.z - h.z); l.w = f2tf32(v.w - h.w);
            int off = buf * A_BUF + aRow[i] * AP + aKq[i] * 4;
            *(float4*)(AH + off) = h;
            *(float4*)(AL + off) = l;
        }
    };
    auto issueB = [&](int k0, int buf) {
#pragma unroll
        for (int i = 0; i < 6; i++) {
            int off = buf * B_BUF + bRow[i] * BP + bCol[i];
            size_t gsrc = (size_t)(k0 + bRow[i]) * N + bn + bCol[i];
            cpasync16((uint32_t)__cvta_generic_to_shared(BH + off), Bhi + gsrc);
            cpasync16((uint32_t)__cvta_generic_to_shared(BL + off), Blo + gsrc);
        }
        CP_COMMIT();
    };
    auto compute = [&](int buf) {
        const float* AHb = AH + buf * A_BUF;
        const float* ALb = AL + buf * A_BUF;
        const float* BHb = BH + buf * B_BUF;
        const float* BLb = BL + buf * B_BUF;
#pragma unroll
        for (int ks = 0; ks < 2; ks++) {
            const int kc = ks * 8;
            // A fragments (m16k8): rows m0w+g, m0w+g+8; cols kc+tg, kc+tg+4
            uint32_t ah[4], al[4];
            {
                int r0 = (m0w + g) * AP + kc + tg;
                int r1 = r0 + 8 * AP;
                ah[0] = __float_as_uint(AHb[r0]);
                ah[1] = __float_as_uint(AHb[r1]);
                ah[2] = __float_as_uint(AHb[r0 + 4]);
                ah[3] = __float_as_uint(AHb[r1 + 4]);
                al[0] = __float_as_uint(ALb[r0]);
                al[1] = __float_as_uint(ALb[r1]);
                al[2] = __float_as_uint(ALb[r0 + 4]);
                al[3] = __float_as_uint(ALb[r1 + 4]);
            }
            const int rk0 = (kc + tg) * BP + g;
            const int rk1 = rk0 + 4 * BP;
#pragma unroll
            for (int nt = 0; nt < 24; nt++) {
                uint32_t bh0 = __float_as_uint(BHb[rk0 + nt * 8]);
                uint32_t bh1 = __float_as_uint(BHb[rk1 + nt * 8]);
                uint32_t bl0 = __float_as_uint(BLb[rk0 + nt * 8]);
                uint32_t bl1 = __float_as_uint(BLb[rk1 + nt * 8]);
                mma8(acc[nt], ah, bh0, bh1);
                mma8(acc[nt], al, bh0, bh1);
                mma8(acc[nt], ah, bl0, bl1);
            }
        }
    };

    // pipeline
    loadA(0);
    issueB(0, 0);
    storeA(0);
    CP_WAIT0();
    __syncthreads();
    int cur = 0;
    for (int k0 = 16; k0 < K; k0 += 16) {
        loadA(k0);
        issueB(k0, cur ^ 1);
        compute(cur);
        storeA(cur ^ 1);
        CP_WAIT0();
        __syncthreads();
        cur ^= 1;
    }
    compute(cur);

    // ---------------- epilogue ----------------
    // lane holds rows r0 = bm+m0w+g, r1 = r0+8; cols bn + nt*8 + 2tg (+1)
    const int lr0 = m0w + g;          // local row
    const int mr0 = bm + lr0;
    const int mr1 = mr0 + 8;
    const int cbase = 2 * tg;         // col within n-tile

    if (MODE == 0) {
        // +bias, then LayerNorm per row (cols distributed across quad lanes)
        float s1a = 0.f, s2a = 0.f, s1b = 0.f, s2b = 0.f;
#pragma unroll
        for (int nt = 0; nt < 24; nt++) {
            int c = nt * 8 + cbase;
            float b0 = __ldg(&bias[c]), b1 = __ldg(&bias[c + 1]);
            float v0 = acc[nt][0] + b0, v1 = acc[nt][1] + b1;
            float v2 = acc[nt][2] + b0, v3 = acc[nt][3] + b1;
            acc[nt][0] = v0; acc[nt][1] = v1; acc[nt][2] = v2; acc[nt][3] = v3;
            s1a += v0 + v1; s2a += v0 * v0 + v1 * v1;
            s1b += v2 + v3; s2b += v2 * v2 + v3 * v3;
        }
#pragma unroll
        for (int o = 1; o < 4; o <<= 1) {
            s1a += __shfl_xor_sync(0xffffffffu, s1a, o);
            s2a += __shfl_xor_sync(0xffffffffu, s2a, o);
            s1b += __shfl_xor_sync(0xffffffffu, s1b, o);
            s2b += __shfl_xor_sync(0xffffffffu, s2b, o);
        }
        float mua  = s1a * (1.0f / 192.0f);
        float inva = rsqrtf(s2a * (1.0f / 192.0f) - mua * mua + 1e-5f);
        float mub  = s1b * (1.0f / 192.0f);
        float invb = rsqrtf(s2b * (1.0f / 192.0f) - mub * mub + 1e-5f);
#pragma unroll
        for (int nt = 0; nt < 24; nt++) {
            int c = nt * 8 + cbase;
            float gg0 = __ldg(&lng[c]), gg1 = __ldg(&lng[c + 1]);
            float bb0 = __ldg(&lnb[c]), bb1 = __ldg(&lnb[c + 1]);
            float2 oa = make_float2((acc[nt][0] - mua) * inva * gg0 + bb0,
                                    (acc[nt][1] - mua) * inva * gg1 + bb1);
            float2 ob = make_float2((acc[nt][2] - mub) * invb * gg0 + bb0,
                                    (acc[nt][3] - mub) * invb * gg1 + bb1);
            *(float2*)(C + (size_t)mr0 * N + c) = oa;
            *(float2*)(C + (size_t)mr1 * N + c) = ob;
        }
    } else if (MODE == 1 || MODE == 2) {
        const float* ct = (MODE == 1) ? g_cos_u : g_cos_d;
        const float* st = (MODE == 1) ? g_sin_u : g_sin_d;
        const int t0 = mr0 & 31;
        const int t1 = mr1 & 31;
#pragma unroll
        for (int nt = 0; nt < 24; nt++) {
            int c = nt * 8 + cbase;
            int p = nt * 4 + tg;
            float c0 = ct[t0 * HALF + p], s0 = st[t0 * HALF + p];
            float c1 = ct[t1 * HALF + p], s1 = st[t1 * HALF + p];
            float2 oa = make_float2(acc[nt][0] * c0 - acc[nt][1] * s0,
                                    acc[nt][1] * c0 + acc[nt][0] * s0);
            float2 ob = make_float2(acc[nt][2] * c1 - acc[nt][3] * s1,
                                    acc[nt][3] * c1 + acc[nt][2] * s1);
            *(float2*)(C + (size_t)mr0 * N + c) = oa;
            *(float2*)(C + (size_t)mr1 * N + c) = ob;
        }
    } else if (MODE == 3) {
#pragma unroll
        for (int nt = 0; nt < 24; nt++) {
            int c = nt * 8 + cbase;
            *(float2*)(C + (size_t)mr0 * N + c) = make_float2(acc[nt][0], acc[nt][1]);
            *(float2*)(C + (size_t)mr1 * N + c) = make_float2(acc[nt][2], acc[nt][3]);
        }
    } else { // MODE 4: +bias +residual, gathered rows
        const int gr0 = x_row_of(mr0);
        const int gr1 = x_row_of(mr1);
#pragma unroll
        for (int nt = 0; nt < 24; nt++) {
            int c = bn + nt * 8 + cbase;
            float b0 = __ldg(&bias[c]), b1 = __ldg(&bias[c + 1]);
            float2 x0 = *(const float2*)(xres + (size_t)gr0 * N + c);
            float2 x1 = *(const float2*)(xres + (size_t)gr1 * N + c);
            *(float2*)(C + (size_t)gr0 * N + c) =
                make_float2(acc[nt][0] + b0 + x0.x, acc[nt][1] + b1 + x0.y);
            *(float2*)(C + (size_t)gr1 * N + c) =
                make_float2(acc[nt][2] + b0 + x1.x, acc[nt][3] + b1 + x1.y);
        }
    }
}

// ---------------- per-sequence retention attention -------------------------
__global__ void __launch_bounds__(256) k_attn(
    const float* __restrict__ Q, const float* __restrict__ Kmat,
    const float* __restrict__ V, float* __restrict__ R)
{
    __shared__ __align__(16) float sKV[SEQ][DH];
    const int q   = blockIdx.x;
    const int tid = threadIdx.x;
    const int n   = tid >> 3;
    const int j   = tid & 7;
    const size_t base = (size_t)q * SEQ * DH;

    for (int i = tid; i < SEQ * DH / 4; i += 256)
        ((float4*)&sKV[0][0])[i] = ((const float4*)(Kmat + base))[i];

    float qr[24];
    const float* qp = Q + base + (size_t)n * DH + j * 24;
#pragma unroll
    for (int dd = 0; dd < 6; dd++)
        *(float4*)&qr[dd * 4] = *(const float4*)(qp + dd * 4);
    __syncthreads();

    float att[SEQ];
#pragma unroll
    for (int m = 0; m < SEQ; m++) {
        float s = 0.0f;
#pragma unroll
        for (int dd = 0; dd < 6; dd++) {
            float4 kv = *(const float4*)&sKV[m][j * 24 + dd * 4];
            s += qr[dd*4+0]*kv.x + qr[dd*4+1]*kv.y + qr[dd*4+2]*kv.z + qr[dd*4+3]*kv.w;
        }
        att[m] = s;
    }
#pragma unroll
    for (int m = 0; m < SEQ; m++) {
#pragma unroll
        for (int o = 1; o < 8; o <<= 1)
            att[m] += __shfl_xor_sync(0xffffffffu, att[m], o);
        att[m] = (n >= m) ? ldexpf(att[m], m - n) : 0.0f;
    }

    __syncthreads();
    for (int i = tid; i < SEQ * DH / 4; i += 256)
        ((float4*)&sKV[0][0])[i] = ((const float4*)(V + base))[i];
    __syncthreads();

    float acc[24];
#pragma unroll
    for (int dd = 0; dd < 24; dd++) acc[dd] = 0.0f;
#pragma unroll
    for (int m = 0; m < SEQ; m++) {
        float a = att[m];
#pragma unroll
        for (int dd = 0; dd < 6; dd++) {
            float4 vv = *(const float4*)&sKV[m][j * 24 + dd * 4];
            acc[dd*4+0] += a * vv.x; acc[dd*4+1] += a * vv.y;
            acc[dd*4+2] += a * vv.z; acc[dd*4+3] += a * vv.w;
        }
    }
    float* rp = R + base + (size_t)n * DH + j * 24;
#pragma unroll
    for (int dd = 0; dd < 6; dd++)
        *(float4*)(rp + dd * 4) = *(const float4*)&acc[dd * 4];
}

// ---------------- launch --------------------------------------------------
extern "C" void kernel_launch(void* const* d_in, const int* in_sizes, int n_in,
                              void* d_out, int out_size)
{
    const float* x    = (const float*)d_in[0];
    const float* W1   = (const float*)d_in[1];
    const float* b1   = (const float*)d_in[2];
    const float* W2   = (const float*)d_in[3];
    const float* b2   = (const float*)d_in[4];
    const float* ln_g = (const float*)d_in[5];
    const float* ln_b = (const float*)d_in[6];
    const float* WQ   = (const float*)d_in[7];
    const float* WK   = (const float*)d_in[8];
    const float* WV   = (const float*)d_in[9];
    float* out = (float*)d_out;

    float* xd = nullptr; cudaGetSymbolAddress((void**)&xd, g_xd);
    float* qb = nullptr; cudaGetSymbolAddress((void**)&qb, g_q);
    float* kb = nullptr; cudaGetSymbolAddress((void**)&kb, g_k);
    float* vb = nullptr; cudaGetSymbolAddress((void**)&vb, g_v);
    float* rb = nullptr; cudaGetSymbolAddress((void**)&rb, g_ret);
    float *w1h, *w1l, *wqh, *wql, *wkh, *wkl, *wvh, *wvl, *w2h, *w2l;
    cudaGetSymbolAddress((void**)&w1h, g_w1h); cudaGetSymbolAddress((void**)&w1l, g_w1l);
    cudaGetSymbolAddress((void**)&wqh, g_wqh); cudaGetSymbolAddress((void**)&wql, g_wql);
    cudaGetSymbolAddress((void**)&wkh, g_wkh); cudaGetSymbolAddress((void**)&wkl, g_wkl);
    cudaGetSymbolAddress((void**)&wvh, g_wvh); cudaGetSymbolAddress((void**)&wvl, g_wvl);
    cudaGetSymbolAddress((void**)&w2h, g_w2h); cudaGetSymbolAddress((void**)&w2l, g_w2l);

    const int SMEM_BYTES = SMEM_FLOATS * 4;   // 71680
    cudaFuncSetAttribute(k_mma<0>, cudaFuncAttributeMaxDynamicSharedMemorySize, SMEM_BYTES);
    cudaFuncSetAttribute(k_mma<1>, cudaFuncAttributeMaxDynamicSharedMemorySize, SMEM_BYTES);
    cudaFuncSetAttribute(k_mma<2>, cudaFuncAttributeMaxDynamicSharedMemorySize, SMEM_BYTES);
    cudaFuncSetAttribute(k_mma<3>, cudaFuncAttributeMaxDynamicSharedMemorySize, SMEM_BYTES);
    cudaFuncSetAttribute(k_mma<4>, cudaFuncAttributeMaxDynamicSharedMemorySize, SMEM_BYTES);

    // prep: weight tf32 split + xPos tables
    {
        int total = DD*DH + 3*DH*DH + DH*DD + SEQ*HALF;
        k_prep<<<(total + 255) / 256, 256>>>(W1, WQ, WK, WV, W2);
    }

    // GEMM1 + bias + fused LN: x(gathered) @ W1 -> g_xd  [M=50176, K=768, N=192]
    k_mma<0><<<dim3(1, MTOT / 64), 128, SMEM_BYTES>>>(x, w1h, w1l, b1, ln_g, ln_b, nullptr, xd, DD, DH);
    // QKV: h @ W{Q,K,V}  [K=192, N=192], xPos fused for Q/K
    k_mma<1><<<dim3(1, MTOT / 64), 128, SMEM_BYTES>>>(xd, wqh, wql, nullptr, nullptr, nullptr, nullptr, qb, DH, DH);
    k_mma<2><<<dim3(1, MTOT / 64), 128, SMEM_BYTES>>>(xd, wkh, wkl, nullptr, nullptr, nullptr, nullptr, kb, DH, DH);
    k_mma<3><<<dim3(1, MTOT / 64), 128, SMEM_BYTES>>>(xd, wvh, wvl, nullptr, nullptr, nullptr, nullptr, vb, DH, DH);
    k_attn<<<NSEQ, 256>>>(qb, kb, vb, rb);
    // GEMM2: ret @ W2 + b2 + x (residual) -> d_out  [K=192, N=768]
    k_mma<4><<<dim3(DD / 192, MTOT / 64), 128, SMEM_BYTES>>>(rb, w2h, w2l, b2, nullptr, nullptr, x, out, DH, DD);
}